// round 12
// baseline (speedup 1.0000x reference)
#include <cuda_runtime.h>
#include <cuda_bf16.h>
#include <cuda_fp16.h>
#include <math.h>
#include <stdint.h>

// ---------------- problem constants ----------------
#define VOCAB     32000
#define N_TOKENS  16
#define TOK_DIM   64
#define NODE_DIM  64
#define HID       128
#define NG        1024
#define MAXN      100000
#define MAXE      1600000

// ---------------- scratch (static device globals; no allocation) ----------------
__device__ __half g_embWp [VOCAB * NODE_DIM];
__device__ __half g_node  [MAXN * NODE_DIM];
__device__ __half g_tmp   [MAXN * HID];
__device__ __half g_x     [MAXN * HID];
__device__ float  g_dis   [MAXN];
__device__ int    g_ctr   [MAXN];
__device__ int    g_rowptr[MAXN + 1];
__device__ unsigned g_csr [MAXE];
__device__ float  g_gsum  [NG * HID];
__device__ float  g_gcnt  [NG];
__device__ __nv_bfloat16 g_wpth[NODE_DIM * TOK_DIM];
__device__ __nv_bfloat16 g_wptl[NODE_DIM * TOK_DIM];
__device__ __half g_wt1h[HID * NODE_DIM];
__device__ __half g_wt1l[HID * NODE_DIM];
__device__ __half g_wt2h[HID * HID];
__device__ __half g_wt2l[HID * HID];

// ================= helpers =================
__device__ __forceinline__ uint32_t smem_u32(const void* p) {
    uint32_t a;
    asm("{ .reg .u64 t; cvta.to.shared.u64 t, %1; cvt.u32.u64 %0, t; }" : "=r"(a) : "l"(p));
    return a;
}
__device__ __forceinline__ void ldsm4(uint32_t (&r)[4], uint32_t addr) {
    asm volatile("ldmatrix.sync.aligned.m8n8.x4.shared.b16 {%0,%1,%2,%3}, [%4];"
                 : "=r"(r[0]), "=r"(r[1]), "=r"(r[2]), "=r"(r[3]) : "r"(addr));
}
__device__ __forceinline__ void mma16816_bf16(float (&d)[4], const uint32_t (&a)[4],
                                              uint32_t b0, uint32_t b1) {
    asm volatile("mma.sync.aligned.m16n8k16.row.col.f32.bf16.bf16.f32 "
                 "{%0,%1,%2,%3}, {%4,%5,%6,%7}, {%8,%9}, {%0,%1,%2,%3};"
                 : "+f"(d[0]), "+f"(d[1]), "+f"(d[2]), "+f"(d[3])
                 : "r"(a[0]), "r"(a[1]), "r"(a[2]), "r"(a[3]), "r"(b0), "r"(b1));
}
__device__ __forceinline__ void mma16816_f16(float (&d)[4], const uint32_t (&a)[4],
                                             uint32_t b0, uint32_t b1) {
    asm volatile("mma.sync.aligned.m16n8k16.row.col.f32.f16.f16.f32 "
                 "{%0,%1,%2,%3}, {%4,%5,%6,%7}, {%8,%9}, {%0,%1,%2,%3};"
                 : "+f"(d[0]), "+f"(d[1]), "+f"(d[2]), "+f"(d[3])
                 : "r"(a[0]), "r"(a[1]), "r"(a[2]), "r"(a[3]), "r"(b0), "r"(b1));
}

// ================= W^T split conversions =================
template<int K, int MOUT>
__global__ void convert_w_bf16_kernel(const float* __restrict__ W,
                                      __nv_bfloat16* __restrict__ hi,
                                      __nv_bfloat16* __restrict__ lo) {
    int i = blockIdx.x * blockDim.x + threadIdx.x;
    if (i >= MOUT * K) return;
    int n = i / K, k = i - n * K;
    float f = W[k * MOUT + n];
    __nv_bfloat16 h = __float2bfloat16(f);
    hi[i] = h;
    lo[i] = __float2bfloat16(f - __bfloat162float(h));
}
template<int K, int MOUT>
__global__ void convert_w_f16_kernel(const float* __restrict__ W,
                                     __half* __restrict__ hi,
                                     __half* __restrict__ lo) {
    int i = blockIdx.x * blockDim.x + threadIdx.x;
    if (i >= MOUT * K) return;
    int n = i / K, k = i - n * K;
    float f = W[k * MOUT + n];
    __half h = __float2half_rn(f);
    hi[i] = h;
    lo[i] = __float2half_rn(f - __half2float(h));
}

// ====== vocab GEMM (fp32 input, split-bf16, fp16 out) ======
template<int K, int MOUT>
__global__ __launch_bounds__(256) void mma_gemm_v_kernel(
    const float* __restrict__ X,
    const __nv_bfloat16* __restrict__ Wth, const __nv_bfloat16* __restrict__ Wtl,
    __half* __restrict__ Y, int N) {
    extern __shared__ char smem[];
    constexpr int P    = K * 2 + 16;
    constexpr int A_HI = 512;
    constexpr int A_LO = A_HI + 128 * P;
    constexpr int B_HI = A_LO + 128 * P;
    constexpr int B_LO = B_HI + MOUT * P;
    constexpr int NT   = MOUT / 16;
    constexpr int NT2  = NT / 2;
    constexpr int KS   = K / 16;
    constexpr int KQ   = K / 4;

    const int tid = threadIdx.x, wid = tid >> 5, lane = tid & 31;
    const int row0 = blockIdx.x * 128;

    for (int idx = tid; idx < 128 * KQ; idx += 256) {
        int r = idx / KQ, kq = idx - r * KQ;
        int row = row0 + r;
        float4 v = (row < N) ? *(const float4*)(X + (long)row * K + kq * 4)
                             : make_float4(0.f, 0.f, 0.f, 0.f);
        float f[4] = {v.x, v.y, v.z, v.w};
        __nv_bfloat16 h[4], l[4];
#pragma unroll
        for (int j = 0; j < 4; j++) {
            h[j] = __float2bfloat16(f[j]);
            l[j] = __float2bfloat16(f[j] - __bfloat162float(h[j]));
        }
        __nv_bfloat162 h01(h[0], h[1]), h23(h[2], h[3]);
        __nv_bfloat162 l01(l[0], l[1]), l23(l[2], l[3]);
        *(uint2*)(smem + A_HI + r * P + kq * 8) = make_uint2(*(uint32_t*)&h01, *(uint32_t*)&h23);
        *(uint2*)(smem + A_LO + r * P + kq * 8) = make_uint2(*(uint32_t*)&l01, *(uint32_t*)&l23);
    }
    for (int idx = tid; idx < MOUT * KQ; idx += 256) {
        int r = idx / KQ, kq = idx - r * KQ;
        *(uint2*)(smem + B_HI + r * P + kq * 8) = *(const uint2*)(Wth + r * K + kq * 4);
        *(uint2*)(smem + B_LO + r * P + kq * 8) = *(const uint2*)(Wtl + r * K + kq * 4);
    }
    __syncthreads();

    const int wm = (wid >> 1) * 32;
    const int wn = (wid & 1) * (MOUT / 2);
    const int grp = lane >> 3, rr = lane & 7;
    const uint32_t sb = smem_u32(smem);
    const uint32_t aH = sb + A_HI + (uint32_t)(wm + (grp & 1) * 8 + rr) * P + ((grp >> 1) * 8) * 2;
    const uint32_t aL = aH + (uint32_t)(A_LO - A_HI);
    const uint32_t bH = sb + B_HI + (uint32_t)(wn + (grp >> 1) * 8 + rr) * P + ((grp & 1) * 8) * 2;
    const uint32_t bL = bH + (uint32_t)(B_LO - B_HI);

    float acc[2][NT][4];
#pragma unroll
    for (int mt = 0; mt < 2; mt++)
#pragma unroll
        for (int nt = 0; nt < NT; nt++)
#pragma unroll
            for (int j = 0; j < 4; j++) acc[mt][nt][j] = 0.f;

#pragma unroll
    for (int ks = 0; ks < KS; ks++) {
        uint32_t ah[2][4], al[2][4], bh[NT2][4], bl[NT2][4];
#pragma unroll
        for (int mt = 0; mt < 2; mt++) {
            ldsm4(ah[mt], aH + mt * 16 * P + ks * 32);
            ldsm4(al[mt], aL + mt * 16 * P + ks * 32);
        }
#pragma unroll
        for (int nt2 = 0; nt2 < NT2; nt2++) {
            ldsm4(bh[nt2], bH + nt2 * 16 * P + ks * 32);
            ldsm4(bl[nt2], bL + nt2 * 16 * P + ks * 32);
        }
#pragma unroll
        for (int mt = 0; mt < 2; mt++)
#pragma unroll
            for (int nt2 = 0; nt2 < NT2; nt2++)
#pragma unroll
                for (int h = 0; h < 2; h++) {
                    float (&d)[4] = acc[mt][nt2 * 2 + h];
                    mma16816_bf16(d, ah[mt], bh[nt2][h * 2], bh[nt2][h * 2 + 1]);
                    mma16816_bf16(d, ah[mt], bl[nt2][h * 2], bl[nt2][h * 2 + 1]);
                    mma16816_bf16(d, al[mt], bh[nt2][h * 2], bh[nt2][h * 2 + 1]);
                }
    }

    const int lrow = lane >> 2;
    const int lcol = (lane & 3) * 2;
#pragma unroll
    for (int mt = 0; mt < 2; mt++) {
        int row = row0 + wm + mt * 16 + lrow;
#pragma unroll
        for (int nt = 0; nt < NT; nt++) {
            int col = wn + nt * 8 + lcol;
            if (row < N)
                *(__half2*)(Y + (long)row * MOUT + col) =
                    __floats2half2_rn(acc[mt][nt][0], acc[mt][nt][1]);
            if (row + 8 < N)
                *(__half2*)(Y + (long)(row + 8) * MOUT + col) =
                    __floats2half2_rn(acc[mt][nt][2], acc[mt][nt][3]);
        }
    }
}

// ====== layer GEMM: fp16 A (exact) x split-fp16 W, 2 MMAs per step, chunked rows ======
// MODE: 1 = bias+relu store fp16, 2 = bias+relu + pooled red into gsum[batch[row]]
// rows processed: [base, Nend)
template<int K, int MODE>
__global__ __launch_bounds__(256) void mma_gemm_h_kernel(
    const __half* __restrict__ X,
    const __half* __restrict__ Wth, const __half* __restrict__ Wtl,
    const float* __restrict__ bias, __half* __restrict__ Y,
    const int* __restrict__ batch, float* __restrict__ gsum, int base, int Nend) {
    extern __shared__ char smem[];
    constexpr int MOUT = HID;
    constexpr int P    = K * 2 + 16;
    constexpr int A_T  = 512;
    constexpr int B_HI = A_T + 128 * P;
    constexpr int B_LO = B_HI + MOUT * P;
    constexpr int NT   = MOUT / 16;
    constexpr int NT2  = NT / 2;
    constexpr int KS   = K / 16;
    constexpr int KQ   = K / 4;

    const int tid = threadIdx.x, wid = tid >> 5, lane = tid & 31;
    const int row0 = base + blockIdx.x * 128;
    float* bs = (float*)smem;
    if (tid < MOUT) bs[tid] = bias[tid];

    for (int idx = tid; idx < 128 * KQ; idx += 256) {
        int r = idx / KQ, kq = idx - r * KQ;
        int row = row0 + r;
        uint2 raw = (row < Nend) ? *(const uint2*)(X + (long)row * K + kq * 4)
                                 : make_uint2(0u, 0u);
        *(uint2*)(smem + A_T + r * P + kq * 8) = raw;
    }
    for (int idx = tid; idx < MOUT * KQ; idx += 256) {
        int r = idx / KQ, kq = idx - r * KQ;
        *(uint2*)(smem + B_HI + r * P + kq * 8) = *(const uint2*)(Wth + r * K + kq * 4);
        *(uint2*)(smem + B_LO + r * P + kq * 8) = *(const uint2*)(Wtl + r * K + kq * 4);
    }
    __syncthreads();

    const int wm = (wid >> 1) * 32;
    const int wn = (wid & 1) * (MOUT / 2);
    const int grp = lane >> 3, rr = lane & 7;
    const uint32_t sb = smem_u32(smem);
    const uint32_t aT = sb + A_T + (uint32_t)(wm + (grp & 1) * 8 + rr) * P + ((grp >> 1) * 8) * 2;
    const uint32_t bH = sb + B_HI + (uint32_t)(wn + (grp >> 1) * 8 + rr) * P + ((grp & 1) * 8) * 2;
    const uint32_t bL = bH + (uint32_t)(B_LO - B_HI);

    float acc[2][NT][4];
#pragma unroll
    for (int mt = 0; mt < 2; mt++)
#pragma unroll
        for (int nt = 0; nt < NT; nt++)
#pragma unroll
            for (int j = 0; j < 4; j++) acc[mt][nt][j] = 0.f;

#pragma unroll
    for (int ks = 0; ks < KS; ks++) {
        uint32_t a[2][4], bh[NT2][4], bl[NT2][4];
#pragma unroll
        for (int mt = 0; mt < 2; mt++)
            ldsm4(a[mt], aT + mt * 16 * P + ks * 32);
#pragma unroll
        for (int nt2 = 0; nt2 < NT2; nt2++) {
            ldsm4(bh[nt2], bH + nt2 * 16 * P + ks * 32);
            ldsm4(bl[nt2], bL + nt2 * 16 * P + ks * 32);
        }
#pragma unroll
        for (int mt = 0; mt < 2; mt++)
#pragma unroll
            for (int nt2 = 0; nt2 < NT2; nt2++)
#pragma unroll
                for (int h = 0; h < 2; h++) {
                    float (&d)[4] = acc[mt][nt2 * 2 + h];
                    mma16816_f16(d, a[mt], bh[nt2][h * 2], bh[nt2][h * 2 + 1]);
                    mma16816_f16(d, a[mt], bl[nt2][h * 2], bl[nt2][h * 2 + 1]);
                }
    }

    const int lrow = lane >> 2;
    const int lcol = (lane & 3) * 2;
#pragma unroll
    for (int mt = 0; mt < 2; mt++) {
        int row = row0 + wm + mt * 16 + lrow;
        int b0i = 0, b1i = 0;
        if (MODE == 2) {
            b0i = (row < Nend)     ? __ldg(batch + row)     : -1;
            b1i = (row + 8 < Nend) ? __ldg(batch + row + 8) : -1;
        }
#pragma unroll
        for (int nt = 0; nt < NT; nt++) {
            int col = wn + nt * 8 + lcol;
            float c0 = bs[col], c1 = bs[col + 1];
            float2 v0 = make_float2(fmaxf(acc[mt][nt][0] + c0, 0.f),
                                    fmaxf(acc[mt][nt][1] + c1, 0.f));
            float2 v1 = make_float2(fmaxf(acc[mt][nt][2] + c0, 0.f),
                                    fmaxf(acc[mt][nt][3] + c1, 0.f));
            if (MODE == 2) {
                if (b0i >= 0) {
                    float* p = gsum + b0i * MOUT + col;
                    asm volatile("red.global.add.v2.f32 [%0], {%1,%2};"
                                 :: "l"(p), "f"(v0.x), "f"(v0.y) : "memory");
                }
                if (b1i >= 0) {
                    float* p = gsum + b1i * MOUT + col;
                    asm volatile("red.global.add.v2.f32 [%0], {%1,%2};"
                                 :: "l"(p), "f"(v1.x), "f"(v1.y) : "memory");
                }
            } else {
                if (row < Nend)
                    *(__half2*)(Y + (long)row * MOUT + col) = __floats2half2_rn(v0.x, v0.y);
                if (row + 8 < Nend)
                    *(__half2*)(Y + (long)(row + 8) * MOUT + col) = __floats2half2_rn(v1.x, v1.y);
            }
        }
    }
}

// ================= token gather + mean pool =================
__global__ void embed_pool_kernel(const int* __restrict__ tokens,
                                  const __half* __restrict__ embWp,
                                  const float* __restrict__ bp,
                                  __half* __restrict__ node, int N) {
    int warp = (blockIdx.x * blockDim.x + threadIdx.x) >> 5;
    int lane = threadIdx.x & 31;
    if (warp >= N) return;
    const int* tp = tokens + warp * N_TOKENS;
    float2 acc = make_float2(0.f, 0.f);
#pragma unroll
    for (int t = 0; t < N_TOKENS; t++) {
        int tok = tp[t];
        float2 f = __half22float2(((const __half2*)embWp)[tok * (NODE_DIM / 2) + lane]);
        acc.x += f.x; acc.y += f.y;
    }
    float2 b = ((const float2*)bp)[lane];
    ((__half2*)node)[warp * (NODE_DIM / 2) + lane] =
        __floats2half2_rn(acc.x * (1.0f / N_TOKENS) + b.x,
                          acc.y * (1.0f / N_TOKENS) + b.y);
}

// ================= CSR build =================
__global__ void hist_kernel(const int* __restrict__ dst, int* __restrict__ ctr, int E) {
    int e = blockIdx.x * blockDim.x + threadIdx.x;
    if (e < E) atomicAdd(ctr + dst[e], 1);
}
// scan also zeroes ctr in place (saves the second memset)
__global__ void scan_kernel(int* __restrict__ deg, int* __restrict__ row_ptr,
                            float* __restrict__ dis, int N) {
    __shared__ int ssum[1024];
    int t = threadIdx.x;
    int chunk = (N + 1023) / 1024;
    int lo = t * chunk;
    int hi = lo + chunk; if (hi > N) hi = N; if (lo > N) lo = N;
    int s = 0;
    for (int i = lo; i < hi; i++) s += deg[i];
    ssum[t] = s;
    __syncthreads();
    for (int off = 1; off < 1024; off <<= 1) {
        int v = (t >= off) ? ssum[t - off] : 0;
        __syncthreads();
        ssum[t] += v;
        __syncthreads();
    }
    int prefix = (t == 0) ? 0 : ssum[t - 1];
    for (int i = lo; i < hi; i++) {
        int d = deg[i];
        row_ptr[i] = prefix;
        dis[i] = rsqrtf((float)(d + 1));
        deg[i] = 0;
        prefix += d;
    }
    if (t == 1023) row_ptr[N] = prefix;
}
__global__ void scatter_kernel(const int* __restrict__ src, const int* __restrict__ dst,
                               const int* __restrict__ row_ptr,
                               int* __restrict__ ctr, unsigned* __restrict__ csr, int E) {
    int e = blockIdx.x * blockDim.x + threadIdx.x;
    if (e >= E) return;
    int s = __ldg(src + e), d = __ldg(dst + e);
    int off = atomicAdd(ctr + d, 1);
    csr[__ldg(row_ptr + d) + off] = (unsigned)s;
}
__global__ void batch_count_kernel(const int* __restrict__ batch, float* __restrict__ gcnt, int N) {
    int i = blockIdx.x * blockDim.x + threadIdx.x;
    if (i < N) atomicAdd(gcnt + batch[i], 1.0f);
}

// ================= CSR aggregation (chunked rows [node0, nodeEnd)) =================
template<int DPL>
__global__ void agg_kernel(const int* __restrict__ row_ptr, const unsigned* __restrict__ csr,
                           const float* __restrict__ dis, const __half* __restrict__ xin,
                           __half* __restrict__ xout, int node0, int nodeEnd) {
    int node = node0 + ((blockIdx.x * blockDim.x + threadIdx.x) >> 5);
    int lane = threadIdx.x & 31;
    if (node >= nodeEnd) return;
    int beg = __ldg(row_ptr + node), end = __ldg(row_ptr + node + 1);
    float di = __ldg(dis + node);
    float w0 = di * di;
    const __half2* xi = (const __half2*)xin;
    float2 acc[DPL];
#pragma unroll
    for (int d = 0; d < DPL; d++) {
        float2 v = __half22float2(xi[(long)node * (32 * DPL) + d * 32 + lane]);
        acc[d] = make_float2(v.x * w0, v.y * w0);
    }
    int j = beg;
    for (; j + 3 < end; j += 4) {
        unsigned s0 = __ldg(csr + j),     s1 = __ldg(csr + j + 1);
        unsigned s2 = __ldg(csr + j + 2), s3 = __ldg(csr + j + 3);
        float wa = __ldg(dis + s0) * di, wb = __ldg(dis + s1) * di;
        float wc = __ldg(dis + s2) * di, wd = __ldg(dis + s3) * di;
#pragma unroll
        for (int d = 0; d < DPL; d++) {
            float2 u0 = __half22float2(xi[(long)s0 * (32 * DPL) + d * 32 + lane]);
            float2 u1 = __half22float2(xi[(long)s1 * (32 * DPL) + d * 32 + lane]);
            float2 u2 = __half22float2(xi[(long)s2 * (32 * DPL) + d * 32 + lane]);
            float2 u3 = __half22float2(xi[(long)s3 * (32 * DPL) + d * 32 + lane]);
            acc[d].x += u0.x * wa + u1.x * wb + u2.x * wc + u3.x * wd;
            acc[d].y += u0.y * wa + u1.y * wb + u2.y * wc + u3.y * wd;
        }
    }
    for (; j < end; j++) {
        unsigned s0 = __ldg(csr + j);
        float wa = __ldg(dis + s0) * di;
#pragma unroll
        for (int d = 0; d < DPL; d++) {
            float2 u0 = __half22float2(xi[(long)s0 * (32 * DPL) + d * 32 + lane]);
            acc[d].x += u0.x * wa; acc[d].y += u0.y * wa;
        }
    }
#pragma unroll
    for (int d = 0; d < DPL; d++)
        ((__half2*)xout)[(long)node * (32 * DPL) + d * 32 + lane] =
            __floats2half2_rn(acc[d].x, acc[d].y);
}

// ================= head =================
__global__ void head_kernel(const float* __restrict__ Wfc, const float* __restrict__ bfc,
                            const float* __restrict__ Wout, const float* __restrict__ bout,
                            float* __restrict__ out, int out_size) {
    __shared__ float gsh[HID];
    __shared__ float red[HID];
    int gid = blockIdx.x;
    int j   = threadIdx.x;
    float cnt = fmaxf(g_gcnt[gid], 1.0f);
    gsh[j] = g_gsum[gid * HID + j] / cnt;
    __syncthreads();
    float acc = bfc[j];
#pragma unroll 8
    for (int k = 0; k < HID; k++) acc += gsh[k] * Wfc[k * HID + j];
    acc = fmaxf(acc, 0.f);
    red[j] = acc * Wout[j];
    __syncthreads();
#pragma unroll
    for (int s = HID / 2; s > 0; s >>= 1) {
        if (j < s) red[j] += red[j + s];
        __syncthreads();
    }
    if (j == 0) {
        float logit = red[0] + bout[0];
        out[gid] = 1.0f / (1.0f + expf(-logit));
        if (out_size >= 2 * NG) out[NG + gid] = logit;
    }
}

// ================= launch =================
extern "C" void kernel_launch(void* const* d_in, const int* in_sizes, int n_in,
                              void* d_out, int out_size) {
    const int*   tokens = (const int*)  d_in[0];
    const int*   eidx   = (const int*)  d_in[1];
    const int*   batch  = (const int*)  d_in[2];
    const float* emb    = (const float*)d_in[3];
    const float* Wp     = (const float*)d_in[4];
    const float* bp     = (const float*)d_in[5];
    const float* W1     = (const float*)d_in[6];
    const float* b1     = (const float*)d_in[7];
    const float* W2     = (const float*)d_in[8];
    const float* b2     = (const float*)d_in[9];
    const float* Wfc    = (const float*)d_in[10];
    const float* bfc    = (const float*)d_in[11];
    const float* Wout   = (const float*)d_in[12];
    const float* bout   = (const float*)d_in[13];
    float* out = (float*)d_out;

    const int N = in_sizes[2];
    const int E = in_sizes[1] / 2;
    const int* src = eidx;
    const int* dst = eidx + E;

    float *dis, *gsum, *gcnt;
    __half *embWp, *node, *tmp, *x;
    int *ctr, *rowptr; unsigned *csr;
    __nv_bfloat16 *wpth, *wptl;
    __half *wt1h, *wt1l, *wt2h, *wt2l;
    cudaGetSymbolAddress((void**)&embWp,  g_embWp);
    cudaGetSymbolAddress((void**)&node,   g_node);
    cudaGetSymbolAddress((void**)&tmp,    g_tmp);
    cudaGetSymbolAddress((void**)&x,      g_x);
    cudaGetSymbolAddress((void**)&dis,    g_dis);
    cudaGetSymbolAddress((void**)&ctr,    g_ctr);
    cudaGetSymbolAddress((void**)&rowptr, g_rowptr);
    cudaGetSymbolAddress((void**)&csr,    g_csr);
    cudaGetSymbolAddress((void**)&gsum,   g_gsum);
    cudaGetSymbolAddress((void**)&gcnt,   g_gcnt);
    cudaGetSymbolAddress((void**)&wpth,   g_wpth);
    cudaGetSymbolAddress((void**)&wptl,   g_wptl);
    cudaGetSymbolAddress((void**)&wt1h,   g_wt1h);
    cudaGetSymbolAddress((void**)&wt1l,   g_wt1l);
    cudaGetSymbolAddress((void**)&wt2h,   g_wt2h);
    cudaGetSymbolAddress((void**)&wt2l,   g_wt2l);

    static cudaStream_t s2 = nullptr;
    static cudaEvent_t evFork = nullptr, evJoin = nullptr, evMain = nullptr;
    static cudaEvent_t evA1 = nullptr, evB1 = nullptr, evA2 = nullptr, evB2 = nullptr;
    if (s2 == nullptr) {
        cudaStreamCreateWithFlags(&s2, cudaStreamNonBlocking);
        cudaEventCreateWithFlags(&evFork, cudaEventDisableTiming);
        cudaEventCreateWithFlags(&evJoin, cudaEventDisableTiming);
        cudaEventCreateWithFlags(&evMain, cudaEventDisableTiming);
        cudaEventCreateWithFlags(&evA1, cudaEventDisableTiming);
        cudaEventCreateWithFlags(&evB1, cudaEventDisableTiming);
        cudaEventCreateWithFlags(&evA2, cudaEventDisableTiming);
        cudaEventCreateWithFlags(&evB2, cudaEventDisableTiming);
    }

    const int SMEM_V   = 512 + 256 * 144 + 2 * 64  * 144;   //  55808
    const int SMEM_H1  = 512 + 128 * 144 + 2 * 128 * 144;   //  55808
    const int SMEM_H2  = 512 + 128 * 272 + 2 * 128 * 272;   // 104960
    cudaFuncSetAttribute((const void*)mma_gemm_v_kernel<64, 64>,
                         cudaFuncAttributeMaxDynamicSharedMemorySize, SMEM_V);
    cudaFuncSetAttribute((const void*)mma_gemm_h_kernel<64, 1>,
                         cudaFuncAttributeMaxDynamicSharedMemorySize, SMEM_H1);
    cudaFuncSetAttribute((const void*)mma_gemm_h_kernel<128, 2>,
                         cudaFuncAttributeMaxDynamicSharedMemorySize, SMEM_H2);

    // ---- fork: CSR build + pooling prep on s2, embedding path on main ----
    cudaEventRecord(evFork, 0);
    cudaStreamWaitEvent(s2, evFork, 0);

    cudaMemsetAsync(ctr, 0, N * sizeof(int), s2);
    cudaMemsetAsync(gsum, 0, NG * HID * sizeof(float), s2);
    cudaMemsetAsync(gcnt, 0, NG * sizeof(float), s2);
    hist_kernel<<<(E + 255) / 256, 256, 0, s2>>>(dst, ctr, E);
    batch_count_kernel<<<(N + 255) / 256, 256, 0, s2>>>(batch, gcnt, N);
    scan_kernel<<<1, 1024, 0, s2>>>(ctr, rowptr, dis, N);  // also zeroes ctr
    scatter_kernel<<<(E + 255) / 256, 256, 0, s2>>>(src, dst, rowptr, ctr, csr, E);
    cudaEventRecord(evJoin, s2);

    // main branch: vocab projection -> embed pool; W1/W2 splits
    convert_w_bf16_kernel<TOK_DIM, NODE_DIM><<<(NODE_DIM * TOK_DIM + 255) / 256, 256>>>(Wp, wpth, wptl);
    mma_gemm_v_kernel<64, 64><<<(VOCAB + 127) / 128, 256, SMEM_V>>>(emb, wpth, wptl, embWp, VOCAB);
    embed_pool_kernel<<<(N * 32 + 255) / 256, 256>>>(tokens, embWp, bp, node, N);
    convert_w_f16_kernel<NODE_DIM, HID><<<(HID * NODE_DIM + 255) / 256, 256>>>(W1, wt1h, wt1l);
    convert_w_f16_kernel<HID, HID><<<(HID * HID + 255) / 256, 256>>>(W2, wt2h, wt2l);
    cudaEventRecord(evMain, 0);

    // cross-waits: both streams need CSR + node + weights
    cudaStreamWaitEvent(0, evJoin, 0);
    cudaStreamWaitEvent(s2, evMain, 0);

    // chunking: 4 chunks of rows (multiple of 128), alternating streams
    const int CH = 4;
    int rows = ((N + CH * 128 - 1) / (CH * 128)) * 128;

    // ---- GCN layer 1 (chunk-pipelined): agg64 -> f16 GEMM 64->128 ----
    for (int k = 0; k < CH; k++) {
        int n0 = k * rows;
        if (n0 >= N) break;
        int nEnd = n0 + rows; if (nEnd > N) nEnd = N;
        int cnt = nEnd - n0;
        cudaStream_t st = (k & 1) ? s2 : 0;
        agg_kernel<1><<<(cnt * 32 + 255) / 256, 256, 0, st>>>(rowptr, csr, dis, node, tmp, n0, nEnd);
        mma_gemm_h_kernel<64, 1><<<(cnt + 127) / 128, 256, SMEM_H1, st>>>(
            tmp, wt1h, wt1l, b1, x, nullptr, nullptr, n0, nEnd);
    }
    cudaEventRecord(evA1, 0);
    cudaEventRecord(evB1, s2);
    cudaStreamWaitEvent(0, evB1, 0);   // stream0 sees all of x
    cudaStreamWaitEvent(s2, evA1, 0);  // s2 sees all of x

    // ---- GCN layer 2 (chunk-pipelined): agg128 -> f16 GEMM + pooled epilogue ----
    for (int k = 0; k < CH; k++) {
        int n0 = k * rows;
        if (n0 >= N) break;
        int nEnd = n0 + rows; if (nEnd > N) nEnd = N;
        int cnt = nEnd - n0;
        cudaStream_t st = (k & 1) ? s2 : 0;
        agg_kernel<2><<<(cnt * 32 + 255) / 256, 256, 0, st>>>(rowptr, csr, dis, x, tmp, n0, nEnd);
        mma_gemm_h_kernel<128, 2><<<(cnt + 127) / 128, 256, SMEM_H2, st>>>(
            tmp, wt2h, wt2l, b2, nullptr, batch, gsum, n0, nEnd);
    }
    cudaEventRecord(evA2, 0);
    cudaEventRecord(evB2, s2);
    cudaStreamWaitEvent(0, evB2, 0);

    // ---- head ----
    head_kernel<<<NG, HID>>>(Wfc, bfc, Wout, bout, out, out_size);
}

// round 13
// speedup vs baseline: 1.0158x; 1.0158x over previous
#include <cuda_runtime.h>
#include <cuda_bf16.h>
#include <cuda_fp16.h>
#include <math.h>
#include <stdint.h>

// ---------------- problem constants ----------------
#define VOCAB     32000
#define N_TOKENS  16
#define TOK_DIM   64
#define NODE_DIM  64
#define HID       128
#define NG        1024
#define MAXN      100000
#define MAXE      1600000

// ---------------- scratch (static device globals; no allocation) ----------------
__device__ __half g_embWp [VOCAB * NODE_DIM];
__device__ __half g_node  [MAXN * NODE_DIM];
__device__ __half g_tmp   [MAXN * HID];
__device__ __half g_x     [MAXN * HID];
__device__ float  g_dis   [MAXN];
__device__ int    g_ctr   [MAXN];
__device__ int    g_rowptr[MAXN + 1];
__device__ unsigned g_csr [MAXE];
__device__ float  g_gsum  [NG * HID];
__device__ float  g_gcnt  [NG];
__device__ __nv_bfloat16 g_wpth[NODE_DIM * TOK_DIM];
__device__ __nv_bfloat16 g_wptl[NODE_DIM * TOK_DIM];
__device__ __half g_wt1h[HID * NODE_DIM];
__device__ __half g_wt1l[HID * NODE_DIM];
__device__ __half g_wt2h[HID * HID];
__device__ __half g_wt2l[HID * HID];

// ================= helpers =================
__device__ __forceinline__ uint32_t smem_u32(const void* p) {
    uint32_t a;
    asm("{ .reg .u64 t; cvta.to.shared.u64 t, %1; cvt.u32.u64 %0, t; }" : "=r"(a) : "l"(p));
    return a;
}
__device__ __forceinline__ void ldsm4(uint32_t (&r)[4], uint32_t addr) {
    asm volatile("ldmatrix.sync.aligned.m8n8.x4.shared.b16 {%0,%1,%2,%3}, [%4];"
                 : "=r"(r[0]), "=r"(r[1]), "=r"(r[2]), "=r"(r[3]) : "r"(addr));
}
__device__ __forceinline__ void mma16816_bf16(float (&d)[4], const uint32_t (&a)[4],
                                              uint32_t b0, uint32_t b1) {
    asm volatile("mma.sync.aligned.m16n8k16.row.col.f32.bf16.bf16.f32 "
                 "{%0,%1,%2,%3}, {%4,%5,%6,%7}, {%8,%9}, {%0,%1,%2,%3};"
                 : "+f"(d[0]), "+f"(d[1]), "+f"(d[2]), "+f"(d[3])
                 : "r"(a[0]), "r"(a[1]), "r"(a[2]), "r"(a[3]), "r"(b0), "r"(b1));
}
__device__ __forceinline__ void mma16816_f16(float (&d)[4], const uint32_t (&a)[4],
                                             uint32_t b0, uint32_t b1) {
    asm volatile("mma.sync.aligned.m16n8k16.row.col.f32.f16.f16.f32 "
                 "{%0,%1,%2,%3}, {%4,%5,%6,%7}, {%8,%9}, {%0,%1,%2,%3};"
                 : "+f"(d[0]), "+f"(d[1]), "+f"(d[2]), "+f"(d[3])
                 : "r"(a[0]), "r"(a[1]), "r"(a[2]), "r"(a[3]), "r"(b0), "r"(b1));
}

// ================= W^T split conversions =================
template<int K, int MOUT>
__global__ void convert_w_bf16_kernel(const float* __restrict__ W,
                                      __nv_bfloat16* __restrict__ hi,
                                      __nv_bfloat16* __restrict__ lo) {
    int i = blockIdx.x * blockDim.x + threadIdx.x;
    if (i >= MOUT * K) return;
    int n = i / K, k = i - n * K;
    float f = W[k * MOUT + n];
    __nv_bfloat16 h = __float2bfloat16(f);
    hi[i] = h;
    lo[i] = __float2bfloat16(f - __bfloat162float(h));
}
template<int K, int MOUT>
__global__ void convert_w_f16_kernel(const float* __restrict__ W,
                                     __half* __restrict__ hi,
                                     __half* __restrict__ lo) {
    int i = blockIdx.x * blockDim.x + threadIdx.x;
    if (i >= MOUT * K) return;
    int n = i / K, k = i - n * K;
    float f = W[k * MOUT + n];
    __half h = __float2half_rn(f);
    hi[i] = h;
    lo[i] = __float2half_rn(f - __half2float(h));
}

// ====== vocab GEMM (fp32 input, split-bf16, fp16 out) ======
template<int K, int MOUT>
__global__ __launch_bounds__(256) void mma_gemm_v_kernel(
    const float* __restrict__ X,
    const __nv_bfloat16* __restrict__ Wth, const __nv_bfloat16* __restrict__ Wtl,
    __half* __restrict__ Y, int N) {
    extern __shared__ char smem[];
    constexpr int P    = K * 2 + 16;
    constexpr int A_HI = 512;
    constexpr int A_LO = A_HI + 128 * P;
    constexpr int B_HI = A_LO + 128 * P;
    constexpr int B_LO = B_HI + MOUT * P;
    constexpr int NT   = MOUT / 16;
    constexpr int NT2  = NT / 2;
    constexpr int KS   = K / 16;
    constexpr int KQ   = K / 4;

    const int tid = threadIdx.x, wid = tid >> 5, lane = tid & 31;
    const int row0 = blockIdx.x * 128;

    for (int idx = tid; idx < 128 * KQ; idx += 256) {
        int r = idx / KQ, kq = idx - r * KQ;
        int row = row0 + r;
        float4 v = (row < N) ? *(const float4*)(X + (long)row * K + kq * 4)
                             : make_float4(0.f, 0.f, 0.f, 0.f);
        float f[4] = {v.x, v.y, v.z, v.w};
        __nv_bfloat16 h[4], l[4];
#pragma unroll
        for (int j = 0; j < 4; j++) {
            h[j] = __float2bfloat16(f[j]);
            l[j] = __float2bfloat16(f[j] - __bfloat162float(h[j]));
        }
        __nv_bfloat162 h01(h[0], h[1]), h23(h[2], h[3]);
        __nv_bfloat162 l01(l[0], l[1]), l23(l[2], l[3]);
        *(uint2*)(smem + A_HI + r * P + kq * 8) = make_uint2(*(uint32_t*)&h01, *(uint32_t*)&h23);
        *(uint2*)(smem + A_LO + r * P + kq * 8) = make_uint2(*(uint32_t*)&l01, *(uint32_t*)&l23);
    }
    for (int idx = tid; idx < MOUT * KQ; idx += 256) {
        int r = idx / KQ, kq = idx - r * KQ;
        *(uint2*)(smem + B_HI + r * P + kq * 8) = *(const uint2*)(Wth + r * K + kq * 4);
        *(uint2*)(smem + B_LO + r * P + kq * 8) = *(const uint2*)(Wtl + r * K + kq * 4);
    }
    __syncthreads();

    const int wm = (wid >> 1) * 32;
    const int wn = (wid & 1) * (MOUT / 2);
    const int grp = lane >> 3, rr = lane & 7;
    const uint32_t sb = smem_u32(smem);
    const uint32_t aH = sb + A_HI + (uint32_t)(wm + (grp & 1) * 8 + rr) * P + ((grp >> 1) * 8) * 2;
    const uint32_t aL = aH + (uint32_t)(A_LO - A_HI);
    const uint32_t bH = sb + B_HI + (uint32_t)(wn + (grp >> 1) * 8 + rr) * P + ((grp & 1) * 8) * 2;
    const uint32_t bL = bH + (uint32_t)(B_LO - B_HI);

    float acc[2][NT][4];
#pragma unroll
    for (int mt = 0; mt < 2; mt++)
#pragma unroll
        for (int nt = 0; nt < NT; nt++)
#pragma unroll
            for (int j = 0; j < 4; j++) acc[mt][nt][j] = 0.f;

#pragma unroll
    for (int ks = 0; ks < KS; ks++) {
        uint32_t ah[2][4], al[2][4], bh[NT2][4], bl[NT2][4];
#pragma unroll
        for (int mt = 0; mt < 2; mt++) {
            ldsm4(ah[mt], aH + mt * 16 * P + ks * 32);
            ldsm4(al[mt], aL + mt * 16 * P + ks * 32);
        }
#pragma unroll
        for (int nt2 = 0; nt2 < NT2; nt2++) {
            ldsm4(bh[nt2], bH + nt2 * 16 * P + ks * 32);
            ldsm4(bl[nt2], bL + nt2 * 16 * P + ks * 32);
        }
#pragma unroll
        for (int mt = 0; mt < 2; mt++)
#pragma unroll
            for (int nt2 = 0; nt2 < NT2; nt2++)
#pragma unroll
                for (int h = 0; h < 2; h++) {
                    float (&d)[4] = acc[mt][nt2 * 2 + h];
                    mma16816_bf16(d, ah[mt], bh[nt2][h * 2], bh[nt2][h * 2 + 1]);
                    mma16816_bf16(d, ah[mt], bl[nt2][h * 2], bl[nt2][h * 2 + 1]);
                    mma16816_bf16(d, al[mt], bh[nt2][h * 2], bh[nt2][h * 2 + 1]);
                }
    }

    const int lrow = lane >> 2;
    const int lcol = (lane & 3) * 2;
#pragma unroll
    for (int mt = 0; mt < 2; mt++) {
        int row = row0 + wm + mt * 16 + lrow;
#pragma unroll
        for (int nt = 0; nt < NT; nt++) {
            int col = wn + nt * 8 + lcol;
            if (row < N)
                *(__half2*)(Y + (long)row * MOUT + col) =
                    __floats2half2_rn(acc[mt][nt][0], acc[mt][nt][1]);
            if (row + 8 < N)
                *(__half2*)(Y + (long)(row + 8) * MOUT + col) =
                    __floats2half2_rn(acc[mt][nt][2], acc[mt][nt][3]);
        }
    }
}

// ====== layer GEMM: fp16 A (exact) x split-fp16 W, 2 MMAs per step ======
// MODE: 1 = bias+relu store fp16, 2 = bias+relu + pooled red into gsum[batch[row]]
template<int K, int MODE>
__global__ __launch_bounds__(256) void mma_gemm_h_kernel(
    const __half* __restrict__ X,
    const __half* __restrict__ Wth, const __half* __restrict__ Wtl,
    const float* __restrict__ bias, __half* __restrict__ Y,
    const int* __restrict__ batch, float* __restrict__ gsum, int N) {
    extern __shared__ char smem[];
    constexpr int MOUT = HID;
    constexpr int P    = K * 2 + 16;
    constexpr int A_T  = 512;
    constexpr int B_HI = A_T + 128 * P;
    constexpr int B_LO = B_HI + MOUT * P;
    constexpr int NT   = MOUT / 16;
    constexpr int NT2  = NT / 2;
    constexpr int KS   = K / 16;
    constexpr int KQ   = K / 4;

    const int tid = threadIdx.x, wid = tid >> 5, lane = tid & 31;
    const int row0 = blockIdx.x * 128;
    float* bs = (float*)smem;
    if (tid < MOUT) bs[tid] = bias[tid];

    for (int idx = tid; idx < 128 * KQ; idx += 256) {
        int r = idx / KQ, kq = idx - r * KQ;
        int row = row0 + r;
        uint2 raw = (row < N) ? *(const uint2*)(X + (long)row * K + kq * 4)
                              : make_uint2(0u, 0u);
        *(uint2*)(smem + A_T + r * P + kq * 8) = raw;
    }
    for (int idx = tid; idx < MOUT * KQ; idx += 256) {
        int r = idx / KQ, kq = idx - r * KQ;
        *(uint2*)(smem + B_HI + r * P + kq * 8) = *(const uint2*)(Wth + r * K + kq * 4);
        *(uint2*)(smem + B_LO + r * P + kq * 8) = *(const uint2*)(Wtl + r * K + kq * 4);
    }
    __syncthreads();

    const int wm = (wid >> 1) * 32;
    const int wn = (wid & 1) * (MOUT / 2);
    const int grp = lane >> 3, rr = lane & 7;
    const uint32_t sb = smem_u32(smem);
    const uint32_t aT = sb + A_T + (uint32_t)(wm + (grp & 1) * 8 + rr) * P + ((grp >> 1) * 8) * 2;
    const uint32_t bH = sb + B_HI + (uint32_t)(wn + (grp >> 1) * 8 + rr) * P + ((grp & 1) * 8) * 2;
    const uint32_t bL = bH + (uint32_t)(B_LO - B_HI);

    float acc[2][NT][4];
#pragma unroll
    for (int mt = 0; mt < 2; mt++)
#pragma unroll
        for (int nt = 0; nt < NT; nt++)
#pragma unroll
            for (int j = 0; j < 4; j++) acc[mt][nt][j] = 0.f;

#pragma unroll
    for (int ks = 0; ks < KS; ks++) {
        uint32_t a[2][4], bh[NT2][4], bl[NT2][4];
#pragma unroll
        for (int mt = 0; mt < 2; mt++)
            ldsm4(a[mt], aT + mt * 16 * P + ks * 32);
#pragma unroll
        for (int nt2 = 0; nt2 < NT2; nt2++) {
            ldsm4(bh[nt2], bH + nt2 * 16 * P + ks * 32);
            ldsm4(bl[nt2], bL + nt2 * 16 * P + ks * 32);
        }
#pragma unroll
        for (int mt = 0; mt < 2; mt++)
#pragma unroll
            for (int nt2 = 0; nt2 < NT2; nt2++)
#pragma unroll
                for (int h = 0; h < 2; h++) {
                    float (&d)[4] = acc[mt][nt2 * 2 + h];
                    mma16816_f16(d, a[mt], bh[nt2][h * 2], bh[nt2][h * 2 + 1]);
                    mma16816_f16(d, a[mt], bl[nt2][h * 2], bl[nt2][h * 2 + 1]);
                }
    }

    const int lrow = lane >> 2;
    const int lcol = (lane & 3) * 2;
#pragma unroll
    for (int mt = 0; mt < 2; mt++) {
        int row = row0 + wm + mt * 16 + lrow;
        int b0i = 0, b1i = 0;
        if (MODE == 2) {
            b0i = (row < N)     ? __ldg(batch + row)     : -1;
            b1i = (row + 8 < N) ? __ldg(batch + row + 8) : -1;
        }
#pragma unroll
        for (int nt = 0; nt < NT; nt++) {
            int col = wn + nt * 8 + lcol;
            float c0 = bs[col], c1 = bs[col + 1];
            float2 v0 = make_float2(fmaxf(acc[mt][nt][0] + c0, 0.f),
                                    fmaxf(acc[mt][nt][1] + c1, 0.f));
            float2 v1 = make_float2(fmaxf(acc[mt][nt][2] + c0, 0.f),
                                    fmaxf(acc[mt][nt][3] + c1, 0.f));
            if (MODE == 2) {
                if (b0i >= 0) {
                    float* p = gsum + b0i * MOUT + col;
                    asm volatile("red.global.add.v2.f32 [%0], {%1,%2};"
                                 :: "l"(p), "f"(v0.x), "f"(v0.y) : "memory");
                }
                if (b1i >= 0) {
                    float* p = gsum + b1i * MOUT + col;
                    asm volatile("red.global.add.v2.f32 [%0], {%1,%2};"
                                 :: "l"(p), "f"(v1.x), "f"(v1.y) : "memory");
                }
            } else {
                if (row < N)
                    *(__half2*)(Y + (long)row * MOUT + col) = __floats2half2_rn(v0.x, v0.y);
                if (row + 8 < N)
                    *(__half2*)(Y + (long)(row + 8) * MOUT + col) = __floats2half2_rn(v1.x, v1.y);
            }
        }
    }
}

// ================= token gather + mean pool (shfl-broadcast indices) =================
__global__ void embed_pool_kernel(const int* __restrict__ tokens,
                                  const __half* __restrict__ embWp,
                                  const float* __restrict__ bp,
                                  __half* __restrict__ node, int N) {
    int warp = (blockIdx.x * blockDim.x + threadIdx.x) >> 5;
    int lane = threadIdx.x & 31;
    if (warp >= N) return;
    // one coalesced load of all 16 token ids, then shfl-broadcast
    int mytok = (lane < N_TOKENS) ? __ldg(tokens + warp * N_TOKENS + lane) : 0;
    float2 acc = make_float2(0.f, 0.f);
#pragma unroll
    for (int t = 0; t < N_TOKENS; t++) {
        int tok = __shfl_sync(0xFFFFFFFFu, mytok, t);
        float2 f = __half22float2(((const __half2*)embWp)[tok * (NODE_DIM / 2) + lane]);
        acc.x += f.x; acc.y += f.y;
    }
    float2 b = ((const float2*)bp)[lane];
    ((__half2*)node)[warp * (NODE_DIM / 2) + lane] =
        __floats2half2_rn(acc.x * (1.0f / N_TOKENS) + b.x,
                          acc.y * (1.0f / N_TOKENS) + b.y);
}

// ================= CSR build =================
__global__ void hist_kernel(const int* __restrict__ dst, int* __restrict__ ctr, int E) {
    int e = blockIdx.x * blockDim.x + threadIdx.x;
    if (e < E) atomicAdd(ctr + dst[e], 1);
}
// scan also zeroes ctr in place (saves the second memset)
__global__ void scan_kernel(int* __restrict__ deg, int* __restrict__ row_ptr,
                            float* __restrict__ dis, int N) {
    __shared__ int ssum[1024];
    int t = threadIdx.x;
    int chunk = (N + 1023) / 1024;
    int lo = t * chunk;
    int hi = lo + chunk; if (hi > N) hi = N; if (lo > N) lo = N;
    int s = 0;
    for (int i = lo; i < hi; i++) s += deg[i];
    ssum[t] = s;
    __syncthreads();
    for (int off = 1; off < 1024; off <<= 1) {
        int v = (t >= off) ? ssum[t - off] : 0;
        __syncthreads();
        ssum[t] += v;
        __syncthreads();
    }
    int prefix = (t == 0) ? 0 : ssum[t - 1];
    for (int i = lo; i < hi; i++) {
        int d = deg[i];
        row_ptr[i] = prefix;
        dis[i] = rsqrtf((float)(d + 1));
        deg[i] = 0;
        prefix += d;
    }
    if (t == 1023) row_ptr[N] = prefix;
}
__global__ void scatter_kernel(const int* __restrict__ src, const int* __restrict__ dst,
                               const int* __restrict__ row_ptr,
                               int* __restrict__ ctr, unsigned* __restrict__ csr, int E) {
    int e = blockIdx.x * blockDim.x + threadIdx.x;
    if (e >= E) return;
    int s = __ldg(src + e), d = __ldg(dst + e);
    int off = atomicAdd(ctr + d, 1);
    csr[__ldg(row_ptr + d) + off] = (unsigned)s;
}
__global__ void batch_count_kernel(const int* __restrict__ batch, float* __restrict__ gcnt, int N) {
    int i = blockIdx.x * blockDim.x + threadIdx.x;
    if (i < N) atomicAdd(gcnt + batch[i], 1.0f);
}

// ================= CSR aggregation (fp16 gather, fp32 accumulate, fp16 out) ===========
template<int DPL>
__global__ void agg_kernel(const int* __restrict__ row_ptr, const unsigned* __restrict__ csr,
                           const float* __restrict__ dis, const __half* __restrict__ xin,
                           __half* __restrict__ xout, int N) {
    int node = (blockIdx.x * blockDim.x + threadIdx.x) >> 5;
    int lane = threadIdx.x & 31;
    if (node >= N) return;
    int beg = __ldg(row_ptr + node), end = __ldg(row_ptr + node + 1);
    float di = __ldg(dis + node);
    float w0 = di * di;
    const __half2* xi = (const __half2*)xin;
    float2 acc[DPL];
#pragma unroll
    for (int d = 0; d < DPL; d++) {
        float2 v = __half22float2(xi[(long)node * (32 * DPL) + d * 32 + lane]);
        acc[d] = make_float2(v.x * w0, v.y * w0);
    }
    int j = beg;
    for (; j + 3 < end; j += 4) {
        unsigned s0 = __ldg(csr + j),     s1 = __ldg(csr + j + 1);
        unsigned s2 = __ldg(csr + j + 2), s3 = __ldg(csr + j + 3);
        float wa = __ldg(dis + s0) * di, wb = __ldg(dis + s1) * di;
        float wc = __ldg(dis + s2) * di, wd = __ldg(dis + s3) * di;
#pragma unroll
        for (int d = 0; d < DPL; d++) {
            float2 u0 = __half22float2(xi[(long)s0 * (32 * DPL) + d * 32 + lane]);
            float2 u1 = __half22float2(xi[(long)s1 * (32 * DPL) + d * 32 + lane]);
            float2 u2 = __half22float2(xi[(long)s2 * (32 * DPL) + d * 32 + lane]);
            float2 u3 = __half22float2(xi[(long)s3 * (32 * DPL) + d * 32 + lane]);
            acc[d].x += u0.x * wa + u1.x * wb + u2.x * wc + u3.x * wd;
            acc[d].y += u0.y * wa + u1.y * wb + u2.y * wc + u3.y * wd;
        }
    }
    for (; j < end; j++) {
        unsigned s0 = __ldg(csr + j);
        float wa = __ldg(dis + s0) * di;
#pragma unroll
        for (int d = 0; d < DPL; d++) {
            float2 u0 = __half22float2(xi[(long)s0 * (32 * DPL) + d * 32 + lane]);
            acc[d].x += u0.x * wa; acc[d].y += u0.y * wa;
        }
    }
#pragma unroll
    for (int d = 0; d < DPL; d++)
        ((__half2*)xout)[(long)node * (32 * DPL) + d * 32 + lane] =
            __floats2half2_rn(acc[d].x, acc[d].y);
}

// ================= head =================
__global__ void head_kernel(const float* __restrict__ Wfc, const float* __restrict__ bfc,
                            const float* __restrict__ Wout, const float* __restrict__ bout,
                            float* __restrict__ out, int out_size) {
    __shared__ float gsh[HID];
    __shared__ float red[HID];
    int gid = blockIdx.x;
    int j   = threadIdx.x;
    float cnt = fmaxf(g_gcnt[gid], 1.0f);
    gsh[j] = g_gsum[gid * HID + j] / cnt;
    __syncthreads();
    float acc = bfc[j];
#pragma unroll 8
    for (int k = 0; k < HID; k++) acc += gsh[k] * Wfc[k * HID + j];
    acc = fmaxf(acc, 0.f);
    red[j] = acc * Wout[j];
    __syncthreads();
#pragma unroll
    for (int s = HID / 2; s > 0; s >>= 1) {
        if (j < s) red[j] += red[j + s];
        __syncthreads();
    }
    if (j == 0) {
        float logit = red[0] + bout[0];
        out[gid] = 1.0f / (1.0f + expf(-logit));
        if (out_size >= 2 * NG) out[NG + gid] = logit;
    }
}

// ================= launch =================
extern "C" void kernel_launch(void* const* d_in, const int* in_sizes, int n_in,
                              void* d_out, int out_size) {
    const int*   tokens = (const int*)  d_in[0];
    const int*   eidx   = (const int*)  d_in[1];
    const int*   batch  = (const int*)  d_in[2];
    const float* emb    = (const float*)d_in[3];
    const float* Wp     = (const float*)d_in[4];
    const float* bp     = (const float*)d_in[5];
    const float* W1     = (const float*)d_in[6];
    const float* b1     = (const float*)d_in[7];
    const float* W2     = (const float*)d_in[8];
    const float* b2     = (const float*)d_in[9];
    const float* Wfc    = (const float*)d_in[10];
    const float* bfc    = (const float*)d_in[11];
    const float* Wout   = (const float*)d_in[12];
    const float* bout   = (const float*)d_in[13];
    float* out = (float*)d_out;

    const int N = in_sizes[2];
    const int E = in_sizes[1] / 2;
    const int* src = eidx;
    const int* dst = eidx + E;

    float *dis, *gsum, *gcnt;
    __half *embWp, *node, *tmp, *x;
    int *ctr, *rowptr; unsigned *csr;
    __nv_bfloat16 *wpth, *wptl;
    __half *wt1h, *wt1l, *wt2h, *wt2l;
    cudaGetSymbolAddress((void**)&embWp,  g_embWp);
    cudaGetSymbolAddress((void**)&node,   g_node);
    cudaGetSymbolAddress((void**)&tmp,    g_tmp);
    cudaGetSymbolAddress((void**)&x,      g_x);
    cudaGetSymbolAddress((void**)&dis,    g_dis);
    cudaGetSymbolAddress((void**)&ctr,    g_ctr);
    cudaGetSymbolAddress((void**)&rowptr, g_rowptr);
    cudaGetSymbolAddress((void**)&csr,    g_csr);
    cudaGetSymbolAddress((void**)&gsum,   g_gsum);
    cudaGetSymbolAddress((void**)&gcnt,   g_gcnt);
    cudaGetSymbolAddress((void**)&wpth,   g_wpth);
    cudaGetSymbolAddress((void**)&wptl,   g_wptl);
    cudaGetSymbolAddress((void**)&wt1h,   g_wt1h);
    cudaGetSymbolAddress((void**)&wt1l,   g_wt1l);
    cudaGetSymbolAddress((void**)&wt2h,   g_wt2h);
    cudaGetSymbolAddress((void**)&wt2l,   g_wt2l);

    static cudaStream_t s2 = nullptr;
    static cudaEvent_t evFork = nullptr, evJoin = nullptr;
    if (s2 == nullptr) {
        cudaStreamCreateWithFlags(&s2, cudaStreamNonBlocking);
        cudaEventCreateWithFlags(&evFork, cudaEventDisableTiming);
        cudaEventCreateWithFlags(&evJoin, cudaEventDisableTiming);
    }

    const int SMEM_V   = 512 + 256 * 144 + 2 * 64  * 144;   //  55808
    const int SMEM_H1  = 512 + 128 * 144 + 2 * 128 * 144;   //  55808
    const int SMEM_H2  = 512 + 128 * 272 + 2 * 128 * 272;   // 104960
    cudaFuncSetAttribute((const void*)mma_gemm_v_kernel<64, 64>,
                         cudaFuncAttributeMaxDynamicSharedMemorySize, SMEM_V);
    cudaFuncSetAttribute((const void*)mma_gemm_h_kernel<64, 1>,
                         cudaFuncAttributeMaxDynamicSharedMemorySize, SMEM_H1);
    cudaFuncSetAttribute((const void*)mma_gemm_h_kernel<128, 2>,
                         cudaFuncAttributeMaxDynamicSharedMemorySize, SMEM_H2);

    // ---- fork: CSR build + pooling prep on s2, embedding path on main ----
    cudaEventRecord(evFork, 0);
    cudaStreamWaitEvent(s2, evFork, 0);

    cudaMemsetAsync(ctr, 0, N * sizeof(int), s2);
    cudaMemsetAsync(gsum, 0, NG * HID * sizeof(float), s2);
    cudaMemsetAsync(gcnt, 0, NG * sizeof(float), s2);
    hist_kernel<<<(E + 255) / 256, 256, 0, s2>>>(dst, ctr, E);
    batch_count_kernel<<<(N + 255) / 256, 256, 0, s2>>>(batch, gcnt, N);
    scan_kernel<<<1, 1024, 0, s2>>>(ctr, rowptr, dis, N);  // also zeroes ctr
    scatter_kernel<<<(E + 255) / 256, 256, 0, s2>>>(src, dst, rowptr, ctr, csr, E);
    cudaEventRecord(evJoin, s2);

    // main branch: vocab projection first (critical path), then W1/W2 splits
    convert_w_bf16_kernel<TOK_DIM, NODE_DIM><<<(NODE_DIM * TOK_DIM + 255) / 256, 256>>>(Wp, wpth, wptl);
    mma_gemm_v_kernel<64, 64><<<(VOCAB + 127) / 128, 256, SMEM_V>>>(emb, wpth, wptl, embWp, VOCAB);
    embed_pool_kernel<<<(N * 32 + 255) / 256, 256>>>(tokens, embWp, bp, node, N);
    convert_w_f16_kernel<NODE_DIM, HID><<<(HID * NODE_DIM + 255) / 256, 256>>>(W1, wt1h, wt1l);
    convert_w_f16_kernel<HID, HID><<<(HID * HID + 255) / 256, 256>>>(W2, wt2h, wt2l);

    cudaStreamWaitEvent(0, evJoin, 0);

    // ---- GCN layer 1: aggregate(64) -> f16 GEMM 64->128 + bias + relu -> fp16 x ----
    agg_kernel<1><<<(N * 32 + 255) / 256, 256>>>(rowptr, csr, dis, node, tmp, N);
    mma_gemm_h_kernel<64, 1><<<(N + 127) / 128, 256, SMEM_H1>>>(
        tmp, wt1h, wt1l, b1, x, nullptr, nullptr, N);

    // ---- GCN layer 2: aggregate(128) -> f16 GEMM + bias + relu + pooled epilogue ----
    agg_kernel<2><<<(N * 32 + 255) / 256, 256>>>(rowptr, csr, dis, x, tmp, N);
    mma_gemm_h_kernel<128, 2><<<(N + 127) / 128, 256, SMEM_H2>>>(
        tmp, wt2h, wt2l, b2, nullptr, batch, gsum, N);

    // ---- head ----
    head_kernel<<<NG, HID>>>(Wfc, bfc, Wout, bout, out, out_size);
}

// round 14
// speedup vs baseline: 1.2395x; 1.2202x over previous
#include <cuda_runtime.h>
#include <cuda_bf16.h>
#include <cuda_fp16.h>
#include <math.h>
#include <stdint.h>

// ---------------- problem constants ----------------
#define VOCAB     32000
#define N_TOKENS  16
#define TOK_DIM   64
#define NODE_DIM  64
#define HID       128
#define NG        1024
#define MAXN      100000
#define MAXE      1600000

// ---------------- scratch (static device globals; no allocation) ----------------
__device__ __half g_embWp [VOCAB * NODE_DIM];
__device__ __half g_node  [MAXN * NODE_DIM];
__device__ __half g_tmp   [MAXN * HID];
__device__ __half g_x     [MAXN * HID];
__device__ float  g_dis   [MAXN];
__device__ int    g_ctr   [MAXN];
__device__ int    g_rowptr[MAXN + 1];
__device__ unsigned g_csr [MAXE];
__device__ float  g_gsum  [NG * HID];
__device__ float  g_gcnt  [NG];
__device__ __nv_bfloat16 g_wpth[NODE_DIM * TOK_DIM];
__device__ __nv_bfloat16 g_wptl[NODE_DIM * TOK_DIM];
__device__ __half g_wt1h[HID * NODE_DIM];
__device__ __half g_wt1l[HID * NODE_DIM];
__device__ __half g_wt2h[HID * HID];
__device__ __half g_wt2l[HID * HID];

// ================= helpers =================
__device__ __forceinline__ uint32_t smem_u32(const void* p) {
    uint32_t a;
    asm("{ .reg .u64 t; cvta.to.shared.u64 t, %1; cvt.u32.u64 %0, t; }" : "=r"(a) : "l"(p));
    return a;
}
__device__ __forceinline__ void ldsm4(uint32_t (&r)[4], uint32_t addr) {
    asm volatile("ldmatrix.sync.aligned.m8n8.x4.shared.b16 {%0,%1,%2,%3}, [%4];"
                 : "=r"(r[0]), "=r"(r[1]), "=r"(r[2]), "=r"(r[3]) : "r"(addr));
}
__device__ __forceinline__ void mma16816_bf16(float (&d)[4], const uint32_t (&a)[4],
                                              uint32_t b0, uint32_t b1) {
    asm volatile("mma.sync.aligned.m16n8k16.row.col.f32.bf16.bf16.f32 "
                 "{%0,%1,%2,%3}, {%4,%5,%6,%7}, {%8,%9}, {%0,%1,%2,%3};"
                 : "+f"(d[0]), "+f"(d[1]), "+f"(d[2]), "+f"(d[3])
                 : "r"(a[0]), "r"(a[1]), "r"(a[2]), "r"(a[3]), "r"(b0), "r"(b1));
}
__device__ __forceinline__ void mma16816_f16(float (&d)[4], const uint32_t (&a)[4],
                                             uint32_t b0, uint32_t b1) {
    asm volatile("mma.sync.aligned.m16n8k16.row.col.f32.f16.f16.f32 "
                 "{%0,%1,%2,%3}, {%4,%5,%6,%7}, {%8,%9}, {%0,%1,%2,%3};"
                 : "+f"(d[0]), "+f"(d[1]), "+f"(d[2]), "+f"(d[3])
                 : "r"(a[0]), "r"(a[1]), "r"(a[2]), "r"(a[3]), "r"(b0), "r"(b1));
}

// ================= W^T split conversions =================
template<int K, int MOUT>
__global__ void convert_w_bf16_kernel(const float* __restrict__ W,
                                      __nv_bfloat16* __restrict__ hi,
                                      __nv_bfloat16* __restrict__ lo) {
    int i = blockIdx.x * blockDim.x + threadIdx.x;
    if (i >= MOUT * K) return;
    int n = i / K, k = i - n * K;
    float f = W[k * MOUT + n];
    __nv_bfloat16 h = __float2bfloat16(f);
    hi[i] = h;
    lo[i] = __float2bfloat16(f - __bfloat162float(h));
}
template<int K, int MOUT>
__global__ void convert_w_f16_kernel(const float* __restrict__ W,
                                     __half* __restrict__ hi,
                                     __half* __restrict__ lo) {
    int i = blockIdx.x * blockDim.x + threadIdx.x;
    if (i >= MOUT * K) return;
    int n = i / K, k = i - n * K;
    float f = W[k * MOUT + n];
    __half h = __float2half_rn(f);
    hi[i] = h;
    lo[i] = __float2half_rn(f - __half2float(h));
}

// ====== vocab GEMM (fp32 input, split-bf16, fp16 out) ======
template<int K, int MOUT>
__global__ __launch_bounds__(256) void mma_gemm_v_kernel(
    const float* __restrict__ X,
    const __nv_bfloat16* __restrict__ Wth, const __nv_bfloat16* __restrict__ Wtl,
    __half* __restrict__ Y, int N) {
    extern __shared__ char smem[];
    constexpr int P    = K * 2 + 16;
    constexpr int A_HI = 512;
    constexpr int A_LO = A_HI + 128 * P;
    constexpr int B_HI = A_LO + 128 * P;
    constexpr int B_LO = B_HI + MOUT * P;
    constexpr int NT   = MOUT / 16;
    constexpr int NT2  = NT / 2;
    constexpr int KS   = K / 16;
    constexpr int KQ   = K / 4;

    const int tid = threadIdx.x, wid = tid >> 5, lane = tid & 31;
    const int row0 = blockIdx.x * 128;

    for (int idx = tid; idx < 128 * KQ; idx += 256) {
        int r = idx / KQ, kq = idx - r * KQ;
        int row = row0 + r;
        float4 v = (row < N) ? *(const float4*)(X + (long)row * K + kq * 4)
                             : make_float4(0.f, 0.f, 0.f, 0.f);
        float f[4] = {v.x, v.y, v.z, v.w};
        __nv_bfloat16 h[4], l[4];
#pragma unroll
        for (int j = 0; j < 4; j++) {
            h[j] = __float2bfloat16(f[j]);
            l[j] = __float2bfloat16(f[j] - __bfloat162float(h[j]));
        }
        __nv_bfloat162 h01(h[0], h[1]), h23(h[2], h[3]);
        __nv_bfloat162 l01(l[0], l[1]), l23(l[2], l[3]);
        *(uint2*)(smem + A_HI + r * P + kq * 8) = make_uint2(*(uint32_t*)&h01, *(uint32_t*)&h23);
        *(uint2*)(smem + A_LO + r * P + kq * 8) = make_uint2(*(uint32_t*)&l01, *(uint32_t*)&l23);
    }
    for (int idx = tid; idx < MOUT * KQ; idx += 256) {
        int r = idx / KQ, kq = idx - r * KQ;
        *(uint2*)(smem + B_HI + r * P + kq * 8) = *(const uint2*)(Wth + r * K + kq * 4);
        *(uint2*)(smem + B_LO + r * P + kq * 8) = *(const uint2*)(Wtl + r * K + kq * 4);
    }
    __syncthreads();

    const int wm = (wid >> 1) * 32;
    const int wn = (wid & 1) * (MOUT / 2);
    const int grp = lane >> 3, rr = lane & 7;
    const uint32_t sb = smem_u32(smem);
    const uint32_t aH = sb + A_HI + (uint32_t)(wm + (grp & 1) * 8 + rr) * P + ((grp >> 1) * 8) * 2;
    const uint32_t aL = aH + (uint32_t)(A_LO - A_HI);
    const uint32_t bH = sb + B_HI + (uint32_t)(wn + (grp >> 1) * 8 + rr) * P + ((grp & 1) * 8) * 2;
    const uint32_t bL = bH + (uint32_t)(B_LO - B_HI);

    float acc[2][NT][4];
#pragma unroll
    for (int mt = 0; mt < 2; mt++)
#pragma unroll
        for (int nt = 0; nt < NT; nt++)
#pragma unroll
            for (int j = 0; j < 4; j++) acc[mt][nt][j] = 0.f;

#pragma unroll
    for (int ks = 0; ks < KS; ks++) {
        uint32_t ah[2][4], al[2][4], bh[NT2][4], bl[NT2][4];
#pragma unroll
        for (int mt = 0; mt < 2; mt++) {
            ldsm4(ah[mt], aH + mt * 16 * P + ks * 32);
            ldsm4(al[mt], aL + mt * 16 * P + ks * 32);
        }
#pragma unroll
        for (int nt2 = 0; nt2 < NT2; nt2++) {
            ldsm4(bh[nt2], bH + nt2 * 16 * P + ks * 32);
            ldsm4(bl[nt2], bL + nt2 * 16 * P + ks * 32);
        }
#pragma unroll
        for (int mt = 0; mt < 2; mt++)
#pragma unroll
            for (int nt2 = 0; nt2 < NT2; nt2++)
#pragma unroll
                for (int h = 0; h < 2; h++) {
                    float (&d)[4] = acc[mt][nt2 * 2 + h];
                    mma16816_bf16(d, ah[mt], bh[nt2][h * 2], bh[nt2][h * 2 + 1]);
                    mma16816_bf16(d, ah[mt], bl[nt2][h * 2], bl[nt2][h * 2 + 1]);
                    mma16816_bf16(d, al[mt], bh[nt2][h * 2], bh[nt2][h * 2 + 1]);
                }
    }

    const int lrow = lane >> 2;
    const int lcol = (lane & 3) * 2;
#pragma unroll
    for (int mt = 0; mt < 2; mt++) {
        int row = row0 + wm + mt * 16 + lrow;
#pragma unroll
        for (int nt = 0; nt < NT; nt++) {
            int col = wn + nt * 8 + lcol;
            if (row < N)
                *(__half2*)(Y + (long)row * MOUT + col) =
                    __floats2half2_rn(acc[mt][nt][0], acc[mt][nt][1]);
            if (row + 8 < N)
                *(__half2*)(Y + (long)(row + 8) * MOUT + col) =
                    __floats2half2_rn(acc[mt][nt][2], acc[mt][nt][3]);
        }
    }
}

// ====== layer GEMM: fp16 A (exact) x split-fp16 W, 2 MMAs per step ======
// MODE: 1 = bias+relu store fp16, 2 = bias+relu + pooled red into gsum[batch[row]]
template<int K, int MODE>
__global__ __launch_bounds__(256) void mma_gemm_h_kernel(
    const __half* __restrict__ X,
    const __half* __restrict__ Wth, const __half* __restrict__ Wtl,
    const float* __restrict__ bias, __half* __restrict__ Y,
    const int* __restrict__ batch, float* __restrict__ gsum, int N) {
    extern __shared__ char smem[];
    constexpr int MOUT = HID;
    constexpr int P    = K * 2 + 16;
    constexpr int A_T  = 512;
    constexpr int B_HI = A_T + 128 * P;
    constexpr int B_LO = B_HI + MOUT * P;
    constexpr int NT   = MOUT / 16;
    constexpr int NT2  = NT / 2;
    constexpr int KS   = K / 16;
    constexpr int KQ   = K / 4;

    const int tid = threadIdx.x, wid = tid >> 5, lane = tid & 31;
    const int row0 = blockIdx.x * 128;
    float* bs = (float*)smem;
    if (tid < MOUT) bs[tid] = bias[tid];

    for (int idx = tid; idx < 128 * KQ; idx += 256) {
        int r = idx / KQ, kq = idx - r * KQ;
        int row = row0 + r;
        uint2 raw = (row < N) ? *(const uint2*)(X + (long)row * K + kq * 4)
                              : make_uint2(0u, 0u);
        *(uint2*)(smem + A_T + r * P + kq * 8) = raw;
    }
    for (int idx = tid; idx < MOUT * KQ; idx += 256) {
        int r = idx / KQ, kq = idx - r * KQ;
        *(uint2*)(smem + B_HI + r * P + kq * 8) = *(const uint2*)(Wth + r * K + kq * 4);
        *(uint2*)(smem + B_LO + r * P + kq * 8) = *(const uint2*)(Wtl + r * K + kq * 4);
    }
    __syncthreads();

    const int wm = (wid >> 1) * 32;
    const int wn = (wid & 1) * (MOUT / 2);
    const int grp = lane >> 3, rr = lane & 7;
    const uint32_t sb = smem_u32(smem);
    const uint32_t aT = sb + A_T + (uint32_t)(wm + (grp & 1) * 8 + rr) * P + ((grp >> 1) * 8) * 2;
    const uint32_t bH = sb + B_HI + (uint32_t)(wn + (grp >> 1) * 8 + rr) * P + ((grp & 1) * 8) * 2;
    const uint32_t bL = bH + (uint32_t)(B_LO - B_HI);

    float acc[2][NT][4];
#pragma unroll
    for (int mt = 0; mt < 2; mt++)
#pragma unroll
        for (int nt = 0; nt < NT; nt++)
#pragma unroll
            for (int j = 0; j < 4; j++) acc[mt][nt][j] = 0.f;

#pragma unroll
    for (int ks = 0; ks < KS; ks++) {
        uint32_t a[2][4], bh[NT2][4], bl[NT2][4];
#pragma unroll
        for (int mt = 0; mt < 2; mt++)
            ldsm4(a[mt], aT + mt * 16 * P + ks * 32);
#pragma unroll
        for (int nt2 = 0; nt2 < NT2; nt2++) {
            ldsm4(bh[nt2], bH + nt2 * 16 * P + ks * 32);
            ldsm4(bl[nt2], bL + nt2 * 16 * P + ks * 32);
        }
#pragma unroll
        for (int mt = 0; mt < 2; mt++)
#pragma unroll
            for (int nt2 = 0; nt2 < NT2; nt2++)
#pragma unroll
                for (int h = 0; h < 2; h++) {
                    float (&d)[4] = acc[mt][nt2 * 2 + h];
                    mma16816_f16(d, a[mt], bh[nt2][h * 2], bh[nt2][h * 2 + 1]);
                    mma16816_f16(d, a[mt], bl[nt2][h * 2], bl[nt2][h * 2 + 1]);
                }
    }

    const int lrow = lane >> 2;
    const int lcol = (lane & 3) * 2;
#pragma unroll
    for (int mt = 0; mt < 2; mt++) {
        int row = row0 + wm + mt * 16 + lrow;
        int b0i = 0, b1i = 0;
        if (MODE == 2) {
            b0i = (row < N)     ? __ldg(batch + row)     : -1;
            b1i = (row + 8 < N) ? __ldg(batch + row + 8) : -1;
        }
#pragma unroll
        for (int nt = 0; nt < NT; nt++) {
            int col = wn + nt * 8 + lcol;
            float c0 = bs[col], c1 = bs[col + 1];
            float2 v0 = make_float2(fmaxf(acc[mt][nt][0] + c0, 0.f),
                                    fmaxf(acc[mt][nt][1] + c1, 0.f));
            float2 v1 = make_float2(fmaxf(acc[mt][nt][2] + c0, 0.f),
                                    fmaxf(acc[mt][nt][3] + c1, 0.f));
            if (MODE == 2) {
                if (b0i >= 0) {
                    float* p = gsum + b0i * MOUT + col;
                    asm volatile("red.global.add.v2.f32 [%0], {%1,%2};"
                                 :: "l"(p), "f"(v0.x), "f"(v0.y) : "memory");
                }
                if (b1i >= 0) {
                    float* p = gsum + b1i * MOUT + col;
                    asm volatile("red.global.add.v2.f32 [%0], {%1,%2};"
                                 :: "l"(p), "f"(v1.x), "f"(v1.y) : "memory");
                }
            } else {
                if (row < N)
                    *(__half2*)(Y + (long)row * MOUT + col) = __floats2half2_rn(v0.x, v0.y);
                if (row + 8 < N)
                    *(__half2*)(Y + (long)(row + 8) * MOUT + col) = __floats2half2_rn(v1.x, v1.y);
            }
        }
    }
}

// ================= token gather + mean pool (R11 form) =================
__global__ void embed_pool_kernel(const int* __restrict__ tokens,
                                  const __half* __restrict__ embWp,
                                  const float* __restrict__ bp,
                                  __half* __restrict__ node, int N) {
    int warp = (blockIdx.x * blockDim.x + threadIdx.x) >> 5;
    int lane = threadIdx.x & 31;
    if (warp >= N) return;
    const int* tp = tokens + warp * N_TOKENS;
    float2 acc = make_float2(0.f, 0.f);
#pragma unroll
    for (int t = 0; t < N_TOKENS; t++) {
        int tok = tp[t];
        float2 f = __half22float2(((const __half2*)embWp)[tok * (NODE_DIM / 2) + lane]);
        acc.x += f.x; acc.y += f.y;
    }
    float2 b = ((const float2*)bp)[lane];
    ((__half2*)node)[warp * (NODE_DIM / 2) + lane] =
        __floats2half2_rn(acc.x * (1.0f / N_TOKENS) + b.x,
                          acc.y * (1.0f / N_TOKENS) + b.y);
}

// ================= CSR build (R11 form) =================
__global__ void hist_kernel(const int* __restrict__ dst, int* __restrict__ ctr, int E) {
    int e = blockIdx.x * blockDim.x + threadIdx.x;
    if (e < E) atomicAdd(ctr + dst[e], 1);
}
__global__ void scan_kernel(const int* __restrict__ deg, int* __restrict__ row_ptr,
                            float* __restrict__ dis, int N) {
    __shared__ int ssum[1024];
    int t = threadIdx.x;
    int chunk = (N + 1023) / 1024;
    int lo = t * chunk;
    int hi = lo + chunk; if (hi > N) hi = N; if (lo > N) lo = N;
    int s = 0;
    for (int i = lo; i < hi; i++) s += deg[i];
    ssum[t] = s;
    __syncthreads();
    for (int off = 1; off < 1024; off <<= 1) {
        int v = (t >= off) ? ssum[t - off] : 0;
        __syncthreads();
        ssum[t] += v;
        __syncthreads();
    }
    int prefix = (t == 0) ? 0 : ssum[t - 1];
    for (int i = lo; i < hi; i++) {
        int d = deg[i];
        row_ptr[i] = prefix;
        dis[i] = rsqrtf((float)(d + 1));
        prefix += d;
    }
    if (t == 1023) row_ptr[N] = prefix;
}
__global__ void scatter_kernel(const int* __restrict__ src, const int* __restrict__ dst,
                               const int* __restrict__ row_ptr,
                               int* __restrict__ ctr, unsigned* __restrict__ csr, int E) {
    int e = blockIdx.x * blockDim.x + threadIdx.x;
    if (e >= E) return;
    int s = __ldg(src + e), d = __ldg(dst + e);
    int off = atomicAdd(ctr + d, 1);
    csr[__ldg(row_ptr + d) + off] = (unsigned)s;
}
__global__ void batch_count_kernel(const int* __restrict__ batch, float* __restrict__ gcnt, int N) {
    int i = blockIdx.x * blockDim.x + threadIdx.x;
    if (i < N) atomicAdd(gcnt + batch[i], 1.0f);
}

// ================= CSR aggregation =================
template<int DPL>
__global__ void agg_kernel(const int* __restrict__ row_ptr, const unsigned* __restrict__ csr,
                           const float* __restrict__ dis, const __half* __restrict__ xin,
                           __half* __restrict__ xout, int N) {
    int node = (blockIdx.x * blockDim.x + threadIdx.x) >> 5;
    int lane = threadIdx.x & 31;
    if (node >= N) return;
    int beg = __ldg(row_ptr + node), end = __ldg(row_ptr + node + 1);
    float di = __ldg(dis + node);
    float w0 = di * di;
    const __half2* xi = (const __half2*)xin;
    float2 acc[DPL];
#pragma unroll
    for (int d = 0; d < DPL; d++) {
        float2 v = __half22float2(xi[(long)node * (32 * DPL) + d * 32 + lane]);
        acc[d] = make_float2(v.x * w0, v.y * w0);
    }
    int j = beg;
    for (; j + 3 < end; j += 4) {
        unsigned s0 = __ldg(csr + j),     s1 = __ldg(csr + j + 1);
        unsigned s2 = __ldg(csr + j + 2), s3 = __ldg(csr + j + 3);
        float wa = __ldg(dis + s0) * di, wb = __ldg(dis + s1) * di;
        float wc = __ldg(dis + s2) * di, wd = __ldg(dis + s3) * di;
#pragma unroll
        for (int d = 0; d < DPL; d++) {
            float2 u0 = __half22float2(xi[(long)s0 * (32 * DPL) + d * 32 + lane]);
            float2 u1 = __half22float2(xi[(long)s1 * (32 * DPL) + d * 32 + lane]);
            float2 u2 = __half22float2(xi[(long)s2 * (32 * DPL) + d * 32 + lane]);
            float2 u3 = __half22float2(xi[(long)s3 * (32 * DPL) + d * 32 + lane]);
            acc[d].x += u0.x * wa + u1.x * wb + u2.x * wc + u3.x * wd;
            acc[d].y += u0.y * wa + u1.y * wb + u2.y * wc + u3.y * wd;
        }
    }
    for (; j < end; j++) {
        unsigned s0 = __ldg(csr + j);
        float wa = __ldg(dis + s0) * di;
#pragma unroll
        for (int d = 0; d < DPL; d++) {
            float2 u0 = __half22float2(xi[(long)s0 * (32 * DPL) + d * 32 + lane]);
            acc[d].x += u0.x * wa; acc[d].y += u0.y * wa;
        }
    }
#pragma unroll
    for (int d = 0; d < DPL; d++)
        ((__half2*)xout)[(long)node * (32 * DPL) + d * 32 + lane] =
            __floats2half2_rn(acc[d].x, acc[d].y);
}

// ================= head =================
__global__ void head_kernel(const float* __restrict__ Wfc, const float* __restrict__ bfc,
                            const float* __restrict__ Wout, const float* __restrict__ bout,
                            float* __restrict__ out, int out_size) {
    __shared__ float gsh[HID];
    __shared__ float red[HID];
    int gid = blockIdx.x;
    int j   = threadIdx.x;
    float cnt = fmaxf(g_gcnt[gid], 1.0f);
    gsh[j] = g_gsum[gid * HID + j] / cnt;
    __syncthreads();
    float acc = bfc[j];
#pragma unroll 8
    for (int k = 0; k < HID; k++) acc += gsh[k] * Wfc[k * HID + j];
    acc = fmaxf(acc, 0.f);
    red[j] = acc * Wout[j];
    __syncthreads();
#pragma unroll
    for (int s = HID / 2; s > 0; s >>= 1) {
        if (j < s) red[j] += red[j + s];
        __syncthreads();
    }
    if (j == 0) {
        float logit = red[0] + bout[0];
        out[gid] = 1.0f / (1.0f + expf(-logit));
        if (out_size >= 2 * NG) out[NG + gid] = logit;
    }
}

// ================= launch =================
extern "C" void kernel_launch(void* const* d_in, const int* in_sizes, int n_in,
                              void* d_out, int out_size) {
    const int*   tokens = (const int*)  d_in[0];
    const int*   eidx   = (const int*)  d_in[1];
    const int*   batch  = (const int*)  d_in[2];
    const float* emb    = (const float*)d_in[3];
    const float* Wp     = (const float*)d_in[4];
    const float* bp     = (const float*)d_in[5];
    const float* W1     = (const float*)d_in[6];
    const float* b1     = (const float*)d_in[7];
    const float* W2     = (const float*)d_in[8];
    const float* b2     = (const float*)d_in[9];
    const float* Wfc    = (const float*)d_in[10];
    const float* bfc    = (const float*)d_in[11];
    const float* Wout   = (const float*)d_in[12];
    const float* bout   = (const float*)d_in[13];
    float* out = (float*)d_out;

    const int N = in_sizes[2];
    const int E = in_sizes[1] / 2;
    const int* src = eidx;
    const int* dst = eidx + E;

    float *dis, *gsum, *gcnt;
    __half *embWp, *node, *tmp, *x;
    int *ctr, *rowptr; unsigned *csr;
    __nv_bfloat16 *wpth, *wptl;
    __half *wt1h, *wt1l, *wt2h, *wt2l;
    cudaGetSymbolAddress((void**)&embWp,  g_embWp);
    cudaGetSymbolAddress((void**)&node,   g_node);
    cudaGetSymbolAddress((void**)&tmp,    g_tmp);
    cudaGetSymbolAddress((void**)&x,      g_x);
    cudaGetSymbolAddress((void**)&dis,    g_dis);
    cudaGetSymbolAddress((void**)&ctr,    g_ctr);
    cudaGetSymbolAddress((void**)&rowptr, g_rowptr);
    cudaGetSymbolAddress((void**)&csr,    g_csr);
    cudaGetSymbolAddress((void**)&gsum,   g_gsum);
    cudaGetSymbolAddress((void**)&gcnt,   g_gcnt);
    cudaGetSymbolAddress((void**)&wpth,   g_wpth);
    cudaGetSymbolAddress((void**)&wptl,   g_wptl);
    cudaGetSymbolAddress((void**)&wt1h,   g_wt1h);
    cudaGetSymbolAddress((void**)&wt1l,   g_wt1l);
    cudaGetSymbolAddress((void**)&wt2h,   g_wt2h);
    cudaGetSymbolAddress((void**)&wt2l,   g_wt2l);

    static cudaStream_t s2 = nullptr;
    static cudaEvent_t evFork = nullptr, evJoin = nullptr, evPool = nullptr;
    if (s2 == nullptr) {
        cudaStreamCreateWithFlags(&s2, cudaStreamNonBlocking);
        cudaEventCreateWithFlags(&evFork, cudaEventDisableTiming);
        cudaEventCreateWithFlags(&evJoin, cudaEventDisableTiming);
        cudaEventCreateWithFlags(&evPool, cudaEventDisableTiming);
    }

    const int SMEM_V   = 512 + 256 * 144 + 2 * 64  * 144;   //  55808
    const int SMEM_H1  = 512 + 128 * 144 + 2 * 128 * 144;   //  55808
    const int SMEM_H2  = 512 + 128 * 272 + 2 * 128 * 272;   // 104960
    cudaFuncSetAttribute((const void*)mma_gemm_v_kernel<64, 64>,
                         cudaFuncAttributeMaxDynamicSharedMemorySize, SMEM_V);
    cudaFuncSetAttribute((const void*)mma_gemm_h_kernel<64, 1>,
                         cudaFuncAttributeMaxDynamicSharedMemorySize, SMEM_H1);
    cudaFuncSetAttribute((const void*)mma_gemm_h_kernel<128, 2>,
                         cudaFuncAttributeMaxDynamicSharedMemorySize, SMEM_H2);

    // ---- fork: CSR build on s2 (join path carries only rowptr/csr/dis) ----
    cudaEventRecord(evFork, 0);
    cudaStreamWaitEvent(s2, evFork, 0);

    cudaMemsetAsync(ctr, 0, N * sizeof(int), s2);
    hist_kernel<<<(E + 255) / 256, 256, 0, s2>>>(dst, ctr, E);
    scan_kernel<<<1, 1024, 0, s2>>>(ctr, rowptr, dis, N);
    cudaMemsetAsync(ctr, 0, N * sizeof(int), s2);
    scatter_kernel<<<(E + 255) / 256, 256, 0, s2>>>(src, dst, rowptr, ctr, csr, E);
    cudaEventRecord(evJoin, s2);

    // pooling prep moved AFTER evJoin (runs in layer-1's shadow)
    cudaMemsetAsync(gsum, 0, NG * HID * sizeof(float), s2);
    cudaMemsetAsync(gcnt, 0, NG * sizeof(float), s2);
    batch_count_kernel<<<(N + 255) / 256, 256, 0, s2>>>(batch, gcnt, N);
    cudaEventRecord(evPool, s2);

    // main branch: vocab projection first (critical path), then W1/W2 splits
    convert_w_bf16_kernel<TOK_DIM, NODE_DIM><<<(NODE_DIM * TOK_DIM + 255) / 256, 256>>>(Wp, wpth, wptl);
    mma_gemm_v_kernel<64, 64><<<(VOCAB + 127) / 128, 256, SMEM_V>>>(emb, wpth, wptl, embWp, VOCAB);
    embed_pool_kernel<<<(N * 32 + 255) / 256, 256>>>(tokens, embWp, bp, node, N);
    convert_w_f16_kernel<NODE_DIM, HID><<<(HID * NODE_DIM + 255) / 256, 256>>>(W1, wt1h, wt1l);
    convert_w_f16_kernel<HID, HID><<<(HID * HID + 255) / 256, 256>>>(W2, wt2h, wt2l);

    cudaStreamWaitEvent(0, evJoin, 0);

    // ---- GCN layer 1: aggregate(64) -> f16 GEMM 64->128 + bias + relu -> fp16 x ----
    agg_kernel<1><<<(N * 32 + 255) / 256, 256>>>(rowptr, csr, dis, node, tmp, N);
    mma_gemm_h_kernel<64, 1><<<(N + 127) / 128, 256, SMEM_H1>>>(
        tmp, wt1h, wt1l, b1, x, nullptr, nullptr, N);

    // ---- GCN layer 2: aggregate(128) -> f16 GEMM + bias + relu + pooled epilogue ----
    agg_kernel<2><<<(N * 32 + 255) / 256, 256>>>(rowptr, csr, dis, x, tmp, N);
    cudaStreamWaitEvent(0, evPool, 0);    // gsum/gcnt ready before pooled GEMM
    mma_gemm_h_kernel<128, 2><<<(N + 127) / 128, 256, SMEM_H2>>>(
        tmp, wt2h, wt2l, b2, nullptr, batch, gsum, N);

    // ---- head ----
    head_kernel<<<NG, HID>>>(Wfc, bfc, Wout, bout, out, out_size);
}

// round 15
// speedup vs baseline: 1.2485x; 1.0073x over previous
#include <cuda_runtime.h>
#include <cuda_bf16.h>
#include <cuda_fp16.h>
#include <math.h>
#include <stdint.h>

// ---------------- problem constants ----------------
#define VOCAB     32000
#define N_TOKENS  16
#define TOK_DIM   64
#define NODE_DIM  64
#define HID       128
#define NG        1024
#define MAXN      100000
#define MAXE      1600000

// ---------------- scratch (static device globals; no allocation) ----------------
__device__ __half g_embWp [VOCAB * NODE_DIM];
__device__ __half g_node  [MAXN * NODE_DIM];
__device__ __half g_tmp   [MAXN * HID];
__device__ __half g_x     [MAXN * HID];
__device__ float  g_dis   [MAXN];
__device__ int    g_ctr   [MAXN];
__device__ int    g_rowptr[MAXN + 1];
__device__ unsigned g_csr [MAXE];
__device__ float  g_gsum  [NG * HID];
__device__ float  g_gcnt  [NG];
__device__ __nv_bfloat16 g_wpth[NODE_DIM * TOK_DIM];
__device__ __nv_bfloat16 g_wptl[NODE_DIM * TOK_DIM];
__device__ __half g_wt1h[HID * NODE_DIM];
__device__ __half g_wt1l[HID * NODE_DIM];
__device__ __half g_wt2h[HID * HID];
__device__ __half g_wt2l[HID * HID];

// ================= helpers =================
__device__ __forceinline__ uint32_t smem_u32(const void* p) {
    uint32_t a;
    asm("{ .reg .u64 t; cvta.to.shared.u64 t, %1; cvt.u32.u64 %0, t; }" : "=r"(a) : "l"(p));
    return a;
}
__device__ __forceinline__ void ldsm4(uint32_t (&r)[4], uint32_t addr) {
    asm volatile("ldmatrix.sync.aligned.m8n8.x4.shared.b16 {%0,%1,%2,%3}, [%4];"
                 : "=r"(r[0]), "=r"(r[1]), "=r"(r[2]), "=r"(r[3]) : "r"(addr));
}
__device__ __forceinline__ void mma16816_bf16(float (&d)[4], const uint32_t (&a)[4],
                                              uint32_t b0, uint32_t b1) {
    asm volatile("mma.sync.aligned.m16n8k16.row.col.f32.bf16.bf16.f32 "
                 "{%0,%1,%2,%3}, {%4,%5,%6,%7}, {%8,%9}, {%0,%1,%2,%3};"
                 : "+f"(d[0]), "+f"(d[1]), "+f"(d[2]), "+f"(d[3])
                 : "r"(a[0]), "r"(a[1]), "r"(a[2]), "r"(a[3]), "r"(b0), "r"(b1));
}
__device__ __forceinline__ void mma16816_f16(float (&d)[4], const uint32_t (&a)[4],
                                             uint32_t b0, uint32_t b1) {
    asm volatile("mma.sync.aligned.m16n8k16.row.col.f32.f16.f16.f32 "
                 "{%0,%1,%2,%3}, {%4,%5,%6,%7}, {%8,%9}, {%0,%1,%2,%3};"
                 : "+f"(d[0]), "+f"(d[1]), "+f"(d[2]), "+f"(d[3])
                 : "r"(a[0]), "r"(a[1]), "r"(a[2]), "r"(a[3]), "r"(b0), "r"(b1));
}

// ================= W^T split conversions =================
template<int K, int MOUT>
__global__ void convert_w_bf16_kernel(const float* __restrict__ W,
                                      __nv_bfloat16* __restrict__ hi,
                                      __nv_bfloat16* __restrict__ lo) {
    int i = blockIdx.x * blockDim.x + threadIdx.x;
    if (i >= MOUT * K) return;
    int n = i / K, k = i - n * K;
    float f = W[k * MOUT + n];
    __nv_bfloat16 h = __float2bfloat16(f);
    hi[i] = h;
    lo[i] = __float2bfloat16(f - __bfloat162float(h));
}
template<int K, int MOUT>
__global__ void convert_w_f16_kernel(const float* __restrict__ W,
                                     __half* __restrict__ hi,
                                     __half* __restrict__ lo) {
    int i = blockIdx.x * blockDim.x + threadIdx.x;
    if (i >= MOUT * K) return;
    int n = i / K, k = i - n * K;
    float f = W[k * MOUT + n];
    __half h = __float2half_rn(f);
    hi[i] = h;
    lo[i] = __float2half_rn(f - __half2float(h));
}

// ====== vocab GEMM (fp32 input, split-bf16, fp16 out) ======
template<int K, int MOUT>
__global__ __launch_bounds__(256) void mma_gemm_v_kernel(
    const float* __restrict__ X,
    const __nv_bfloat16* __restrict__ Wth, const __nv_bfloat16* __restrict__ Wtl,
    __half* __restrict__ Y, int N) {
    extern __shared__ char smem[];
    constexpr int P    = K * 2 + 16;
    constexpr int A_HI = 512;
    constexpr int A_LO = A_HI + 128 * P;
    constexpr int B_HI = A_LO + 128 * P;
    constexpr int B_LO = B_HI + MOUT * P;
    constexpr int NT   = MOUT / 16;
    constexpr int NT2  = NT / 2;
    constexpr int KS   = K / 16;
    constexpr int KQ   = K / 4;

    const int tid = threadIdx.x, wid = tid >> 5, lane = tid & 31;
    const int row0 = blockIdx.x * 128;

    for (int idx = tid; idx < 128 * KQ; idx += 256) {
        int r = idx / KQ, kq = idx - r * KQ;
        int row = row0 + r;
        float4 v = (row < N) ? *(const float4*)(X + (long)row * K + kq * 4)
                             : make_float4(0.f, 0.f, 0.f, 0.f);
        float f[4] = {v.x, v.y, v.z, v.w};
        __nv_bfloat16 h[4], l[4];
#pragma unroll
        for (int j = 0; j < 4; j++) {
            h[j] = __float2bfloat16(f[j]);
            l[j] = __float2bfloat16(f[j] - __bfloat162float(h[j]));
        }
        __nv_bfloat162 h01(h[0], h[1]), h23(h[2], h[3]);
        __nv_bfloat162 l01(l[0], l[1]), l23(l[2], l[3]);
        *(uint2*)(smem + A_HI + r * P + kq * 8) = make_uint2(*(uint32_t*)&h01, *(uint32_t*)&h23);
        *(uint2*)(smem + A_LO + r * P + kq * 8) = make_uint2(*(uint32_t*)&l01, *(uint32_t*)&l23);
    }
    for (int idx = tid; idx < MOUT * KQ; idx += 256) {
        int r = idx / KQ, kq = idx - r * KQ;
        *(uint2*)(smem + B_HI + r * P + kq * 8) = *(const uint2*)(Wth + r * K + kq * 4);
        *(uint2*)(smem + B_LO + r * P + kq * 8) = *(const uint2*)(Wtl + r * K + kq * 4);
    }
    __syncthreads();

    const int wm = (wid >> 1) * 32;
    const int wn = (wid & 1) * (MOUT / 2);
    const int grp = lane >> 3, rr = lane & 7;
    const uint32_t sb = smem_u32(smem);
    const uint32_t aH = sb + A_HI + (uint32_t)(wm + (grp & 1) * 8 + rr) * P + ((grp >> 1) * 8) * 2;
    const uint32_t aL = aH + (uint32_t)(A_LO - A_HI);
    const uint32_t bH = sb + B_HI + (uint32_t)(wn + (grp >> 1) * 8 + rr) * P + ((grp & 1) * 8) * 2;
    const uint32_t bL = bH + (uint32_t)(B_LO - B_HI);

    float acc[2][NT][4];
#pragma unroll
    for (int mt = 0; mt < 2; mt++)
#pragma unroll
        for (int nt = 0; nt < NT; nt++)
#pragma unroll
            for (int j = 0; j < 4; j++) acc[mt][nt][j] = 0.f;

#pragma unroll
    for (int ks = 0; ks < KS; ks++) {
        uint32_t ah[2][4], al[2][4], bh[NT2][4], bl[NT2][4];
#pragma unroll
        for (int mt = 0; mt < 2; mt++) {
            ldsm4(ah[mt], aH + mt * 16 * P + ks * 32);
            ldsm4(al[mt], aL + mt * 16 * P + ks * 32);
        }
#pragma unroll
        for (int nt2 = 0; nt2 < NT2; nt2++) {
            ldsm4(bh[nt2], bH + nt2 * 16 * P + ks * 32);
            ldsm4(bl[nt2], bL + nt2 * 16 * P + ks * 32);
        }
#pragma unroll
        for (int mt = 0; mt < 2; mt++)
#pragma unroll
            for (int nt2 = 0; nt2 < NT2; nt2++)
#pragma unroll
                for (int h = 0; h < 2; h++) {
                    float (&d)[4] = acc[mt][nt2 * 2 + h];
                    mma16816_bf16(d, ah[mt], bh[nt2][h * 2], bh[nt2][h * 2 + 1]);
                    mma16816_bf16(d, ah[mt], bl[nt2][h * 2], bl[nt2][h * 2 + 1]);
                    mma16816_bf16(d, al[mt], bh[nt2][h * 2], bh[nt2][h * 2 + 1]);
                }
    }

    const int lrow = lane >> 2;
    const int lcol = (lane & 3) * 2;
#pragma unroll
    for (int mt = 0; mt < 2; mt++) {
        int row = row0 + wm + mt * 16 + lrow;
#pragma unroll
        for (int nt = 0; nt < NT; nt++) {
            int col = wn + nt * 8 + lcol;
            if (row < N)
                *(__half2*)(Y + (long)row * MOUT + col) =
                    __floats2half2_rn(acc[mt][nt][0], acc[mt][nt][1]);
            if (row + 8 < N)
                *(__half2*)(Y + (long)(row + 8) * MOUT + col) =
                    __floats2half2_rn(acc[mt][nt][2], acc[mt][nt][3]);
        }
    }
}

// ====== layer GEMM: fp16 A (exact) x split-fp16 W, 2 MMAs per step ======
template<int K, int MODE>
__global__ __launch_bounds__(256) void mma_gemm_h_kernel(
    const __half* __restrict__ X,
    const __half* __restrict__ Wth, const __half* __restrict__ Wtl,
    const float* __restrict__ bias, __half* __restrict__ Y,
    const int* __restrict__ batch, float* __restrict__ gsum, int N) {
    extern __shared__ char smem[];
    constexpr int MOUT = HID;
    constexpr int P    = K * 2 + 16;
    constexpr int A_T  = 512;
    constexpr int B_HI = A_T + 128 * P;
    constexpr int B_LO = B_HI + MOUT * P;
    constexpr int NT   = MOUT / 16;
    constexpr int NT2  = NT / 2;
    constexpr int KS   = K / 16;
    constexpr int KQ   = K / 4;

    const int tid = threadIdx.x, wid = tid >> 5, lane = tid & 31;
    const int row0 = blockIdx.x * 128;
    float* bs = (float*)smem;
    if (tid < MOUT) bs[tid] = bias[tid];

    for (int idx = tid; idx < 128 * KQ; idx += 256) {
        int r = idx / KQ, kq = idx - r * KQ;
        int row = row0 + r;
        uint2 raw = (row < N) ? *(const uint2*)(X + (long)row * K + kq * 4)
                              : make_uint2(0u, 0u);
        *(uint2*)(smem + A_T + r * P + kq * 8) = raw;
    }
    for (int idx = tid; idx < MOUT * KQ; idx += 256) {
        int r = idx / KQ, kq = idx - r * KQ;
        *(uint2*)(smem + B_HI + r * P + kq * 8) = *(const uint2*)(Wth + r * K + kq * 4);
        *(uint2*)(smem + B_LO + r * P + kq * 8) = *(const uint2*)(Wtl + r * K + kq * 4);
    }
    __syncthreads();

    const int wm = (wid >> 1) * 32;
    const int wn = (wid & 1) * (MOUT / 2);
    const int grp = lane >> 3, rr = lane & 7;
    const uint32_t sb = smem_u32(smem);
    const uint32_t aT = sb + A_T + (uint32_t)(wm + (grp & 1) * 8 + rr) * P + ((grp >> 1) * 8) * 2;
    const uint32_t bH = sb + B_HI + (uint32_t)(wn + (grp >> 1) * 8 + rr) * P + ((grp & 1) * 8) * 2;
    const uint32_t bL = bH + (uint32_t)(B_LO - B_HI);

    float acc[2][NT][4];
#pragma unroll
    for (int mt = 0; mt < 2; mt++)
#pragma unroll
        for (int nt = 0; nt < NT; nt++)
#pragma unroll
            for (int j = 0; j < 4; j++) acc[mt][nt][j] = 0.f;

#pragma unroll
    for (int ks = 0; ks < KS; ks++) {
        uint32_t a[2][4], bh[NT2][4], bl[NT2][4];
#pragma unroll
        for (int mt = 0; mt < 2; mt++)
            ldsm4(a[mt], aT + mt * 16 * P + ks * 32);
#pragma unroll
        for (int nt2 = 0; nt2 < NT2; nt2++) {
            ldsm4(bh[nt2], bH + nt2 * 16 * P + ks * 32);
            ldsm4(bl[nt2], bL + nt2 * 16 * P + ks * 32);
        }
#pragma unroll
        for (int mt = 0; mt < 2; mt++)
#pragma unroll
            for (int nt2 = 0; nt2 < NT2; nt2++)
#pragma unroll
                for (int h = 0; h < 2; h++) {
                    float (&d)[4] = acc[mt][nt2 * 2 + h];
                    mma16816_f16(d, a[mt], bh[nt2][h * 2], bh[nt2][h * 2 + 1]);
                    mma16816_f16(d, a[mt], bl[nt2][h * 2], bl[nt2][h * 2 + 1]);
                }
    }

    const int lrow = lane >> 2;
    const int lcol = (lane & 3) * 2;
#pragma unroll
    for (int mt = 0; mt < 2; mt++) {
        int row = row0 + wm + mt * 16 + lrow;
        int b0i = 0, b1i = 0;
        if (MODE == 2) {
            b0i = (row < N)     ? __ldg(batch + row)     : -1;
            b1i = (row + 8 < N) ? __ldg(batch + row + 8) : -1;
        }
#pragma unroll
        for (int nt = 0; nt < NT; nt++) {
            int col = wn + nt * 8 + lcol;
            float c0 = bs[col], c1 = bs[col + 1];
            float2 v0 = make_float2(fmaxf(acc[mt][nt][0] + c0, 0.f),
                                    fmaxf(acc[mt][nt][1] + c1, 0.f));
            float2 v1 = make_float2(fmaxf(acc[mt][nt][2] + c0, 0.f),
                                    fmaxf(acc[mt][nt][3] + c1, 0.f));
            if (MODE == 2) {
                if (b0i >= 0) {
                    float* p = gsum + b0i * MOUT + col;
                    asm volatile("red.global.add.v2.f32 [%0], {%1,%2};"
                                 :: "l"(p), "f"(v0.x), "f"(v0.y) : "memory");
                }
                if (b1i >= 0) {
                    float* p = gsum + b1i * MOUT + col;
                    asm volatile("red.global.add.v2.f32 [%0], {%1,%2};"
                                 :: "l"(p), "f"(v1.x), "f"(v1.y) : "memory");
                }
            } else {
                if (row < N)
                    *(__half2*)(Y + (long)row * MOUT + col) = __floats2half2_rn(v0.x, v0.y);
                if (row + 8 < N)
                    *(__half2*)(Y + (long)(row + 8) * MOUT + col) = __floats2half2_rn(v1.x, v1.y);
            }
        }
    }
}

// ================= token gather + mean pool =================
__global__ void embed_pool_kernel(const int* __restrict__ tokens,
                                  const __half* __restrict__ embWp,
                                  const float* __restrict__ bp,
                                  __half* __restrict__ node, int N) {
    int warp = (blockIdx.x * blockDim.x + threadIdx.x) >> 5;
    int lane = threadIdx.x & 31;
    if (warp >= N) return;
    const int* tp = tokens + warp * N_TOKENS;
    float2 acc = make_float2(0.f, 0.f);
#pragma unroll
    for (int t = 0; t < N_TOKENS; t++) {
        int tok = tp[t];
        float2 f = __half22float2(((const __half2*)embWp)[tok * (NODE_DIM / 2) + lane]);
        acc.x += f.x; acc.y += f.y;
    }
    float2 b = ((const float2*)bp)[lane];
    ((__half2*)node)[warp * (NODE_DIM / 2) + lane] =
        __floats2half2_rn(acc.x * (1.0f / N_TOKENS) + b.x,
                          acc.y * (1.0f / N_TOKENS) + b.y);
}

// ================= CSR build =================
__global__ void hist_kernel(const int* __restrict__ dst, int* __restrict__ ctr, int E) {
    int e = blockIdx.x * blockDim.x + threadIdx.x;
    if (e < E) atomicAdd(ctr + dst[e], 1);
}
__global__ void scan_kernel(const int* __restrict__ deg, int* __restrict__ row_ptr,
                            float* __restrict__ dis, int N) {
    __shared__ int ssum[1024];
    int t = threadIdx.x;
    int chunk = (N + 1023) / 1024;
    int lo = t * chunk;
    int hi = lo + chunk; if (hi > N) hi = N; if (lo > N) lo = N;
    int s = 0;
    for (int i = lo; i < hi; i++) s += deg[i];
    ssum[t] = s;
    __syncthreads();
    for (int off = 1; off < 1024; off <<= 1) {
        int v = (t >= off) ? ssum[t - off] : 0;
        __syncthreads();
        ssum[t] += v;
        __syncthreads();
    }
    int prefix = (t == 0) ? 0 : ssum[t - 1];
    for (int i = lo; i < hi; i++) {
        int d = deg[i];
        row_ptr[i] = prefix;
        dis[i] = rsqrtf((float)(d + 1));
        prefix += d;
    }
    if (t == 1023) row_ptr[N] = prefix;
}
__global__ void scatter_kernel(const int* __restrict__ src, const int* __restrict__ dst,
                               const int* __restrict__ row_ptr,
                               int* __restrict__ ctr, unsigned* __restrict__ csr, int E) {
    int e = blockIdx.x * blockDim.x + threadIdx.x;
    if (e >= E) return;
    int s = __ldg(src + e), d = __ldg(dst + e);
    int off = atomicAdd(ctr + d, 1);
    csr[__ldg(row_ptr + d) + off] = (unsigned)s;
}
// warp-aggregated: batch is sorted, most lanes in a warp share the same graph id
__global__ void batch_count_kernel(const int* __restrict__ batch, float* __restrict__ gcnt, int N) {
    int i = blockIdx.x * blockDim.x + threadIdx.x;
    if (i >= N) return;
    int b = batch[i];
    unsigned act = __activemask();
    unsigned mask = __match_any_sync(act, b);
    int leader = __ffs(mask) - 1;
    if ((int)(threadIdx.x & 31) == leader)
        atomicAdd(gcnt + b, (float)__popc(mask));
}

// ================= CSR aggregation (8-way edge unroll) =================
template<int DPL>
__global__ void agg_kernel(const int* __restrict__ row_ptr, const unsigned* __restrict__ csr,
                           const float* __restrict__ dis, const __half* __restrict__ xin,
                           __half* __restrict__ xout, int N) {
    int node = (blockIdx.x * blockDim.x + threadIdx.x) >> 5;
    int lane = threadIdx.x & 31;
    if (node >= N) return;
    int beg = __ldg(row_ptr + node), end = __ldg(row_ptr + node + 1);
    float di = __ldg(dis + node);
    float w0 = di * di;
    const __half2* xi = (const __half2*)xin;
    float2 acc[DPL];
#pragma unroll
    for (int d = 0; d < DPL; d++) {
        float2 v = __half22float2(xi[(long)node * (32 * DPL) + d * 32 + lane]);
        acc[d] = make_float2(v.x * w0, v.y * w0);
    }
    int j = beg;
    for (; j + 7 < end; j += 8) {
        unsigned s[8];
        float w[8];
#pragma unroll
        for (int q = 0; q < 8; q++) s[q] = __ldg(csr + j + q);
#pragma unroll
        for (int q = 0; q < 8; q++) w[q] = __ldg(dis + s[q]) * di;
#pragma unroll
        for (int d = 0; d < DPL; d++) {
            float2 u[8];
#pragma unroll
            for (int q = 0; q < 8; q++)
                u[q] = __half22float2(xi[(long)s[q] * (32 * DPL) + d * 32 + lane]);
#pragma unroll
            for (int q = 0; q < 8; q++) {
                acc[d].x += u[q].x * w[q];
                acc[d].y += u[q].y * w[q];
            }
        }
    }
    for (; j + 1 < end; j += 2) {
        unsigned s0 = __ldg(csr + j), s1 = __ldg(csr + j + 1);
        float wa = __ldg(dis + s0) * di, wb = __ldg(dis + s1) * di;
#pragma unroll
        for (int d = 0; d < DPL; d++) {
            float2 u0 = __half22float2(xi[(long)s0 * (32 * DPL) + d * 32 + lane]);
            float2 u1 = __half22float2(xi[(long)s1 * (32 * DPL) + d * 32 + lane]);
            acc[d].x += u0.x * wa + u1.x * wb;
            acc[d].y += u0.y * wa + u1.y * wb;
        }
    }
    if (j < end) {
        unsigned s0 = __ldg(csr + j);
        float wa = __ldg(dis + s0) * di;
#pragma unroll
        for (int d = 0; d < DPL; d++) {
            float2 u0 = __half22float2(xi[(long)s0 * (32 * DPL) + d * 32 + lane]);
            acc[d].x += u0.x * wa; acc[d].y += u0.y * wa;
        }
    }
#pragma unroll
    for (int d = 0; d < DPL; d++)
        ((__half2*)xout)[(long)node * (32 * DPL) + d * 32 + lane] =
            __floats2half2_rn(acc[d].x, acc[d].y);
}

// ================= head =================
__global__ void head_kernel(const float* __restrict__ Wfc, const float* __restrict__ bfc,
                            const float* __restrict__ Wout, const float* __restrict__ bout,
                            float* __restrict__ out, int out_size) {
    __shared__ float gsh[HID];
    __shared__ float red[HID];
    int gid = blockIdx.x;
    int j   = threadIdx.x;
    float cnt = fmaxf(g_gcnt[gid], 1.0f);
    gsh[j] = g_gsum[gid * HID + j] / cnt;
    __syncthreads();
    float acc = bfc[j];
#pragma unroll 8
    for (int k = 0; k < HID; k++) acc += gsh[k] * Wfc[k * HID + j];
    acc = fmaxf(acc, 0.f);
    red[j] = acc * Wout[j];
    __syncthreads();
#pragma unroll
    for (int s = HID / 2; s > 0; s >>= 1) {
        if (j < s) red[j] += red[j + s];
        __syncthreads();
    }
    if (j == 0) {
        float logit = red[0] + bout[0];
        out[gid] = 1.0f / (1.0f + expf(-logit));
        if (out_size >= 2 * NG) out[NG + gid] = logit;
    }
}

// ================= launch =================
extern "C" void kernel_launch(void* const* d_in, const int* in_sizes, int n_in,
                              void* d_out, int out_size) {
    const int*   tokens = (const int*)  d_in[0];
    const int*   eidx   = (const int*)  d_in[1];
    const int*   batch  = (const int*)  d_in[2];
    const float* emb    = (const float*)d_in[3];
    const float* Wp     = (const float*)d_in[4];
    const float* bp     = (const float*)d_in[5];
    const float* W1     = (const float*)d_in[6];
    const float* b1     = (const float*)d_in[7];
    const float* W2     = (const float*)d_in[8];
    const float* b2     = (const float*)d_in[9];
    const float* Wfc    = (const float*)d_in[10];
    const float* bfc    = (const float*)d_in[11];
    const float* Wout   = (const float*)d_in[12];
    const float* bout   = (const float*)d_in[13];
    float* out = (float*)d_out;

    const int N = in_sizes[2];
    const int E = in_sizes[1] / 2;
    const int* src = eidx;
    const int* dst = eidx + E;

    float *dis, *gsum, *gcnt;
    __half *embWp, *node, *tmp, *x;
    int *ctr, *rowptr; unsigned *csr;
    __nv_bfloat16 *wpth, *wptl;
    __half *wt1h, *wt1l, *wt2h, *wt2l;
    cudaGetSymbolAddress((void**)&embWp,  g_embWp);
    cudaGetSymbolAddress((void**)&node,   g_node);
    cudaGetSymbolAddress((void**)&tmp,    g_tmp);
    cudaGetSymbolAddress((void**)&x,      g_x);
    cudaGetSymbolAddress((void**)&dis,    g_dis);
    cudaGetSymbolAddress((void**)&ctr,    g_ctr);
    cudaGetSymbolAddress((void**)&rowptr, g_rowptr);
    cudaGetSymbolAddress((void**)&csr,    g_csr);
    cudaGetSymbolAddress((void**)&gsum,   g_gsum);
    cudaGetSymbolAddress((void**)&gcnt,   g_gcnt);
    cudaGetSymbolAddress((void**)&wpth,   g_wpth);
    cudaGetSymbolAddress((void**)&wptl,   g_wptl);
    cudaGetSymbolAddress((void**)&wt1h,   g_wt1h);
    cudaGetSymbolAddress((void**)&wt1l,   g_wt1l);
    cudaGetSymbolAddress((void**)&wt2h,   g_wt2h);
    cudaGetSymbolAddress((void**)&wt2l,   g_wt2l);

    static cudaStream_t s2 = nullptr;
    static cudaEvent_t evFork = nullptr, evJoin = nullptr, evPool = nullptr;
    if (s2 == nullptr) {
        cudaStreamCreateWithFlags(&s2, cudaStreamNonBlocking);
        cudaEventCreateWithFlags(&evFork, cudaEventDisableTiming);
        cudaEventCreateWithFlags(&evJoin, cudaEventDisableTiming);
        cudaEventCreateWithFlags(&evPool, cudaEventDisableTiming);
    }

    const int SMEM_V   = 512 + 256 * 144 + 2 * 64  * 144;   //  55808
    const int SMEM_H1  = 512 + 128 * 144 + 2 * 128 * 144;   //  55808
    const int SMEM_H2  = 512 + 128 * 272 + 2 * 128 * 272;   // 104960
    cudaFuncSetAttribute((const void*)mma_gemm_v_kernel<64, 64>,
                         cudaFuncAttributeMaxDynamicSharedMemorySize, SMEM_V);
    cudaFuncSetAttribute((const void*)mma_gemm_h_kernel<64, 1>,
                         cudaFuncAttributeMaxDynamicSharedMemorySize, SMEM_H1);
    cudaFuncSetAttribute((const void*)mma_gemm_h_kernel<128, 2>,
                         cudaFuncAttributeMaxDynamicSharedMemorySize, SMEM_H2);

    // ---- fork: CSR build on s2 (join path carries only rowptr/csr/dis) ----
    cudaEventRecord(evFork, 0);
    cudaStreamWaitEvent(s2, evFork, 0);

    cudaMemsetAsync(ctr, 0, N * sizeof(int), s2);
    hist_kernel<<<(E + 255) / 256, 256, 0, s2>>>(dst, ctr, E);
    scan_kernel<<<1, 1024, 0, s2>>>(ctr, rowptr, dis, N);
    cudaMemsetAsync(ctr, 0, N * sizeof(int), s2);
    scatter_kernel<<<(E + 255) / 256, 256, 0, s2>>>(src, dst, rowptr, ctr, csr, E);
    cudaEventRecord(evJoin, s2);

    // pooling prep AFTER evJoin (runs in layer-1's shadow)
    cudaMemsetAsync(gsum, 0, NG * HID * sizeof(float), s2);
    cudaMemsetAsync(gcnt, 0, NG * sizeof(float), s2);
    batch_count_kernel<<<(N + 255) / 256, 256, 0, s2>>>(batch, gcnt, N);
    cudaEventRecord(evPool, s2);

    // main branch: vocab projection first (critical path), then W1/W2 splits
    convert_w_bf16_kernel<TOK_DIM, NODE_DIM><<<(NODE_DIM * TOK_DIM + 255) / 256, 256>>>(Wp, wpth, wptl);
    mma_gemm_v_kernel<64, 64><<<(VOCAB + 127) / 128, 256, SMEM_V>>>(emb, wpth, wptl, embWp, VOCAB);
    embed_pool_kernel<<<(N * 32 + 255) / 256, 256>>>(tokens, embWp, bp, node, N);
    convert_w_f16_kernel<NODE_DIM, HID><<<(HID * NODE_DIM + 255) / 256, 256>>>(W1, wt1h, wt1l);
    convert_w_f16_kernel<HID, HID><<<(HID * HID + 255) / 256, 256>>>(W2, wt2h, wt2l);

    cudaStreamWaitEvent(0, evJoin, 0);

    // ---- GCN layer 1: aggregate(64) -> f16 GEMM 64->128 + bias + relu -> fp16 x ----
    agg_kernel<1><<<(N * 32 + 255) / 256, 256>>>(rowptr, csr, dis, node, tmp, N);
    mma_gemm_h_kernel<64, 1><<<(N + 127) / 128, 256, SMEM_H1>>>(
        tmp, wt1h, wt1l, b1, x, nullptr, nullptr, N);

    // ---- GCN layer 2: aggregate(128) -> f16 GEMM + bias + relu + pooled epilogue ----
    agg_kernel<2><<<(N * 32 + 255) / 256, 256>>>(rowptr, csr, dis, x, tmp, N);
    cudaStreamWaitEvent(0, evPool, 0);
    mma_gemm_h_kernel<128, 2><<<(N + 127) / 128, 256, SMEM_H2>>>(
        tmp, wt2h, wt2l, b2, nullptr, batch, gsum, N);

    // ---- head ----
    head_kernel<<<NG, HID>>>(Wfc, bfc, Wout, bout, out, out_size);
}

// round 16
// speedup vs baseline: 1.2835x; 1.0280x over previous
#include <cuda_runtime.h>
#include <cuda_bf16.h>
#include <cuda_fp16.h>
#include <math.h>
#include <stdint.h>

// ---------------- problem constants ----------------
#define VOCAB     32000
#define N_TOKENS  16
#define TOK_DIM   64
#define NODE_DIM  64
#define HID       128
#define NG        1024
#define MAXN      100000
#define MAXE      1600000

// ---------------- scratch (static device globals; no allocation) ----------------
__device__ __half g_embWp [VOCAB * NODE_DIM];
__device__ __half g_node  [MAXN * NODE_DIM];
__device__ __half g_tmp   [MAXN * HID];
__device__ __half g_x     [MAXN * HID];
__device__ float  g_dis   [MAXN];
__device__ int    g_ctr   [MAXN];
__device__ int    g_rowptr[MAXN + 1];
__device__ unsigned g_csr [MAXE];
__device__ float  g_gsum  [NG * HID];
__device__ float  g_gcnt  [NG];
__device__ __nv_bfloat16 g_wpth[NODE_DIM * TOK_DIM];
__device__ __nv_bfloat16 g_wptl[NODE_DIM * TOK_DIM];
__device__ __half g_wt1h[HID * NODE_DIM];
__device__ __half g_wt1l[HID * NODE_DIM];
__device__ __half g_wt2h[HID * HID];
__device__ __half g_wt2l[HID * HID];

// ================= helpers =================
__device__ __forceinline__ uint32_t smem_u32(const void* p) {
    uint32_t a;
    asm("{ .reg .u64 t; cvta.to.shared.u64 t, %1; cvt.u32.u64 %0, t; }" : "=r"(a) : "l"(p));
    return a;
}
__device__ __forceinline__ void ldsm4(uint32_t (&r)[4], uint32_t addr) {
    asm volatile("ldmatrix.sync.aligned.m8n8.x4.shared.b16 {%0,%1,%2,%3}, [%4];"
                 : "=r"(r[0]), "=r"(r[1]), "=r"(r[2]), "=r"(r[3]) : "r"(addr));
}
__device__ __forceinline__ void mma16816_bf16(float (&d)[4], const uint32_t (&a)[4],
                                              uint32_t b0, uint32_t b1) {
    asm volatile("mma.sync.aligned.m16n8k16.row.col.f32.bf16.bf16.f32 "
                 "{%0,%1,%2,%3}, {%4,%5,%6,%7}, {%8,%9}, {%0,%1,%2,%3};"
                 : "+f"(d[0]), "+f"(d[1]), "+f"(d[2]), "+f"(d[3])
                 : "r"(a[0]), "r"(a[1]), "r"(a[2]), "r"(a[3]), "r"(b0), "r"(b1));
}
__device__ __forceinline__ void mma16816_f16(float (&d)[4], const uint32_t (&a)[4],
                                             uint32_t b0, uint32_t b1) {
    asm volatile("mma.sync.aligned.m16n8k16.row.col.f32.f16.f16.f32 "
                 "{%0,%1,%2,%3}, {%4,%5,%6,%7}, {%8,%9}, {%0,%1,%2,%3};"
                 : "+f"(d[0]), "+f"(d[1]), "+f"(d[2]), "+f"(d[3])
                 : "r"(a[0]), "r"(a[1]), "r"(a[2]), "r"(a[3]), "r"(b0), "r"(b1));
}

// ================= W^T split conversions =================
template<int K, int MOUT>
__global__ void convert_w_bf16_kernel(const float* __restrict__ W,
                                      __nv_bfloat16* __restrict__ hi,
                                      __nv_bfloat16* __restrict__ lo) {
    int i = blockIdx.x * blockDim.x + threadIdx.x;
    if (i >= MOUT * K) return;
    int n = i / K, k = i - n * K;
    float f = W[k * MOUT + n];
    __nv_bfloat16 h = __float2bfloat16(f);
    hi[i] = h;
    lo[i] = __float2bfloat16(f - __bfloat162float(h));
}
template<int K, int MOUT>
__global__ void convert_w_f16_kernel(const float* __restrict__ W,
                                     __half* __restrict__ hi,
                                     __half* __restrict__ lo) {
    int i = blockIdx.x * blockDim.x + threadIdx.x;
    if (i >= MOUT * K) return;
    int n = i / K, k = i - n * K;
    float f = W[k * MOUT + n];
    __half h = __float2half_rn(f);
    hi[i] = h;
    lo[i] = __float2half_rn(f - __half2float(h));
}

// ====== vocab GEMM (fp32 input, split-bf16, fp16 out) ======
template<int K, int MOUT>
__global__ __launch_bounds__(256) void mma_gemm_v_kernel(
    const float* __restrict__ X,
    const __nv_bfloat16* __restrict__ Wth, const __nv_bfloat16* __restrict__ Wtl,
    __half* __restrict__ Y, int N) {
    extern __shared__ char smem[];
    constexpr int P    = K * 2 + 16;
    constexpr int A_HI = 512;
    constexpr int A_LO = A_HI + 128 * P;
    constexpr int B_HI = A_LO + 128 * P;
    constexpr int B_LO = B_HI + MOUT * P;
    constexpr int NT   = MOUT / 16;
    constexpr int NT2  = NT / 2;
    constexpr int KS   = K / 16;
    constexpr int KQ   = K / 4;

    const int tid = threadIdx.x, wid = tid >> 5, lane = tid & 31;
    const int row0 = blockIdx.x * 128;

    for (int idx = tid; idx < 128 * KQ; idx += 256) {
        int r = idx / KQ, kq = idx - r * KQ;
        int row = row0 + r;
        float4 v = (row < N) ? *(const float4*)(X + (long)row * K + kq * 4)
                             : make_float4(0.f, 0.f, 0.f, 0.f);
        float f[4] = {v.x, v.y, v.z, v.w};
        __nv_bfloat16 h[4], l[4];
#pragma unroll
        for (int j = 0; j < 4; j++) {
            h[j] = __float2bfloat16(f[j]);
            l[j] = __float2bfloat16(f[j] - __bfloat162float(h[j]));
        }
        __nv_bfloat162 h01(h[0], h[1]), h23(h[2], h[3]);
        __nv_bfloat162 l01(l[0], l[1]), l23(l[2], l[3]);
        *(uint2*)(smem + A_HI + r * P + kq * 8) = make_uint2(*(uint32_t*)&h01, *(uint32_t*)&h23);
        *(uint2*)(smem + A_LO + r * P + kq * 8) = make_uint2(*(uint32_t*)&l01, *(uint32_t*)&l23);
    }
    for (int idx = tid; idx < MOUT * KQ; idx += 256) {
        int r = idx / KQ, kq = idx - r * KQ;
        *(uint2*)(smem + B_HI + r * P + kq * 8) = *(const uint2*)(Wth + r * K + kq * 4);
        *(uint2*)(smem + B_LO + r * P + kq * 8) = *(const uint2*)(Wtl + r * K + kq * 4);
    }
    __syncthreads();

    const int wm = (wid >> 1) * 32;
    const int wn = (wid & 1) * (MOUT / 2);
    const int grp = lane >> 3, rr = lane & 7;
    const uint32_t sb = smem_u32(smem);
    const uint32_t aH = sb + A_HI + (uint32_t)(wm + (grp & 1) * 8 + rr) * P + ((grp >> 1) * 8) * 2;
    const uint32_t aL = aH + (uint32_t)(A_LO - A_HI);
    const uint32_t bH = sb + B_HI + (uint32_t)(wn + (grp >> 1) * 8 + rr) * P + ((grp & 1) * 8) * 2;
    const uint32_t bL = bH + (uint32_t)(B_LO - B_HI);

    float acc[2][NT][4];
#pragma unroll
    for (int mt = 0; mt < 2; mt++)
#pragma unroll
        for (int nt = 0; nt < NT; nt++)
#pragma unroll
            for (int j = 0; j < 4; j++) acc[mt][nt][j] = 0.f;

#pragma unroll
    for (int ks = 0; ks < KS; ks++) {
        uint32_t ah[2][4], al[2][4], bh[NT2][4], bl[NT2][4];
#pragma unroll
        for (int mt = 0; mt < 2; mt++) {
            ldsm4(ah[mt], aH + mt * 16 * P + ks * 32);
            ldsm4(al[mt], aL + mt * 16 * P + ks * 32);
        }
#pragma unroll
        for (int nt2 = 0; nt2 < NT2; nt2++) {
            ldsm4(bh[nt2], bH + nt2 * 16 * P + ks * 32);
            ldsm4(bl[nt2], bL + nt2 * 16 * P + ks * 32);
        }
#pragma unroll
        for (int mt = 0; mt < 2; mt++)
#pragma unroll
            for (int nt2 = 0; nt2 < NT2; nt2++)
#pragma unroll
                for (int h = 0; h < 2; h++) {
                    float (&d)[4] = acc[mt][nt2 * 2 + h];
                    mma16816_bf16(d, ah[mt], bh[nt2][h * 2], bh[nt2][h * 2 + 1]);
                    mma16816_bf16(d, ah[mt], bl[nt2][h * 2], bl[nt2][h * 2 + 1]);
                    mma16816_bf16(d, al[mt], bh[nt2][h * 2], bh[nt2][h * 2 + 1]);
                }
    }

    const int lrow = lane >> 2;
    const int lcol = (lane & 3) * 2;
#pragma unroll
    for (int mt = 0; mt < 2; mt++) {
        int row = row0 + wm + mt * 16 + lrow;
#pragma unroll
        for (int nt = 0; nt < NT; nt++) {
            int col = wn + nt * 8 + lcol;
            if (row < N)
                *(__half2*)(Y + (long)row * MOUT + col) =
                    __floats2half2_rn(acc[mt][nt][0], acc[mt][nt][1]);
            if (row + 8 < N)
                *(__half2*)(Y + (long)(row + 8) * MOUT + col) =
                    __floats2half2_rn(acc[mt][nt][2], acc[mt][nt][3]);
        }
    }
}

// ====== layer GEMM: fp16 A (exact) x split-fp16 W, 2 MMAs per step ======
template<int K, int MODE>
__global__ __launch_bounds__(256) void mma_gemm_h_kernel(
    const __half* __restrict__ X,
    const __half* __restrict__ Wth, const __half* __restrict__ Wtl,
    const float* __restrict__ bias, __half* __restrict__ Y,
    const int* __restrict__ batch, float* __restrict__ gsum, int N) {
    extern __shared__ char smem[];
    constexpr int MOUT = HID;
    constexpr int P    = K * 2 + 16;
    constexpr int A_T  = 512;
    constexpr int B_HI = A_T + 128 * P;
    constexpr int B_LO = B_HI + MOUT * P;
    constexpr int NT   = MOUT / 16;
    constexpr int NT2  = NT / 2;
    constexpr int KS   = K / 16;
    constexpr int KQ   = K / 4;

    const int tid = threadIdx.x, wid = tid >> 5, lane = tid & 31;
    const int row0 = blockIdx.x * 128;
    float* bs = (float*)smem;
    if (tid < MOUT) bs[tid] = bias[tid];

    for (int idx = tid; idx < 128 * KQ; idx += 256) {
        int r = idx / KQ, kq = idx - r * KQ;
        int row = row0 + r;
        uint2 raw = (row < N) ? *(const uint2*)(X + (long)row * K + kq * 4)
                              : make_uint2(0u, 0u);
        *(uint2*)(smem + A_T + r * P + kq * 8) = raw;
    }
    for (int idx = tid; idx < MOUT * KQ; idx += 256) {
        int r = idx / KQ, kq = idx - r * KQ;
        *(uint2*)(smem + B_HI + r * P + kq * 8) = *(const uint2*)(Wth + r * K + kq * 4);
        *(uint2*)(smem + B_LO + r * P + kq * 8) = *(const uint2*)(Wtl + r * K + kq * 4);
    }
    __syncthreads();

    const int wm = (wid >> 1) * 32;
    const int wn = (wid & 1) * (MOUT / 2);
    const int grp = lane >> 3, rr = lane & 7;
    const uint32_t sb = smem_u32(smem);
    const uint32_t aT = sb + A_T + (uint32_t)(wm + (grp & 1) * 8 + rr) * P + ((grp >> 1) * 8) * 2;
    const uint32_t bH = sb + B_HI + (uint32_t)(wn + (grp >> 1) * 8 + rr) * P + ((grp & 1) * 8) * 2;
    const uint32_t bL = bH + (uint32_t)(B_LO - B_HI);

    float acc[2][NT][4];
#pragma unroll
    for (int mt = 0; mt < 2; mt++)
#pragma unroll
        for (int nt = 0; nt < NT; nt++)
#pragma unroll
            for (int j = 0; j < 4; j++) acc[mt][nt][j] = 0.f;

#pragma unroll
    for (int ks = 0; ks < KS; ks++) {
        uint32_t a[2][4], bh[NT2][4], bl[NT2][4];
#pragma unroll
        for (int mt = 0; mt < 2; mt++)
            ldsm4(a[mt], aT + mt * 16 * P + ks * 32);
#pragma unroll
        for (int nt2 = 0; nt2 < NT2; nt2++) {
            ldsm4(bh[nt2], bH + nt2 * 16 * P + ks * 32);
            ldsm4(bl[nt2], bL + nt2 * 16 * P + ks * 32);
        }
#pragma unroll
        for (int mt = 0; mt < 2; mt++)
#pragma unroll
            for (int nt2 = 0; nt2 < NT2; nt2++)
#pragma unroll
                for (int h = 0; h < 2; h++) {
                    float (&d)[4] = acc[mt][nt2 * 2 + h];
                    mma16816_f16(d, a[mt], bh[nt2][h * 2], bh[nt2][h * 2 + 1]);
                    mma16816_f16(d, a[mt], bl[nt2][h * 2], bl[nt2][h * 2 + 1]);
                }
    }

    const int lrow = lane >> 2;
    const int lcol = (lane & 3) * 2;
#pragma unroll
    for (int mt = 0; mt < 2; mt++) {
        int row = row0 + wm + mt * 16 + lrow;
        int b0i = 0, b1i = 0;
        if (MODE == 2) {
            b0i = (row < N)     ? __ldg(batch + row)     : -1;
            b1i = (row + 8 < N) ? __ldg(batch + row + 8) : -1;
        }
#pragma unroll
        for (int nt = 0; nt < NT; nt++) {
            int col = wn + nt * 8 + lcol;
            float c0 = bs[col], c1 = bs[col + 1];
            float2 v0 = make_float2(fmaxf(acc[mt][nt][0] + c0, 0.f),
                                    fmaxf(acc[mt][nt][1] + c1, 0.f));
            float2 v1 = make_float2(fmaxf(acc[mt][nt][2] + c0, 0.f),
                                    fmaxf(acc[mt][nt][3] + c1, 0.f));
            if (MODE == 2) {
                if (b0i >= 0) {
                    float* p = gsum + b0i * MOUT + col;
                    asm volatile("red.global.add.v2.f32 [%0], {%1,%2};"
                                 :: "l"(p), "f"(v0.x), "f"(v0.y) : "memory");
                }
                if (b1i >= 0) {
                    float* p = gsum + b1i * MOUT + col;
                    asm volatile("red.global.add.v2.f32 [%0], {%1,%2};"
                                 :: "l"(p), "f"(v1.x), "f"(v1.y) : "memory");
                }
            } else {
                if (row < N)
                    *(__half2*)(Y + (long)row * MOUT + col) = __floats2half2_rn(v0.x, v0.y);
                if (row + 8 < N)
                    *(__half2*)(Y + (long)(row + 8) * MOUT + col) = __floats2half2_rn(v1.x, v1.y);
            }
        }
    }
}

// ================= token gather + mean pool =================
__global__ void embed_pool_kernel(const int* __restrict__ tokens,
                                  const __half* __restrict__ embWp,
                                  const float* __restrict__ bp,
                                  __half* __restrict__ node, int N) {
    int warp = (blockIdx.x * blockDim.x + threadIdx.x) >> 5;
    int lane = threadIdx.x & 31;
    if (warp >= N) return;
    const int* tp = tokens + warp * N_TOKENS;
    float2 acc = make_float2(0.f, 0.f);
#pragma unroll
    for (int t = 0; t < N_TOKENS; t++) {
        int tok = tp[t];
        float2 f = __half22float2(((const __half2*)embWp)[tok * (NODE_DIM / 2) + lane]);
        acc.x += f.x; acc.y += f.y;
    }
    float2 b = ((const float2*)bp)[lane];
    ((__half2*)node)[warp * (NODE_DIM / 2) + lane] =
        __floats2half2_rn(acc.x * (1.0f / N_TOKENS) + b.x,
                          acc.y * (1.0f / N_TOKENS) + b.y);
}

// ================= CSR build =================
__global__ void hist_kernel(const int* __restrict__ dst, int* __restrict__ ctr, int E) {
    int e = blockIdx.x * blockDim.x + threadIdx.x;
    if (e < E) atomicAdd(ctr + dst[e], 1);
}
__global__ void scan_kernel(const int* __restrict__ deg, int* __restrict__ row_ptr,
                            float* __restrict__ dis, int N) {
    __shared__ int ssum[1024];
    int t = threadIdx.x;
    int chunk = (N + 1023) / 1024;
    int lo = t * chunk;
    int hi = lo + chunk; if (hi > N) hi = N; if (lo > N) lo = N;
    int s = 0;
    for (int i = lo; i < hi; i++) s += deg[i];
    ssum[t] = s;
    __syncthreads();
    for (int off = 1; off < 1024; off <<= 1) {
        int v = (t >= off) ? ssum[t - off] : 0;
        __syncthreads();
        ssum[t] += v;
        __syncthreads();
    }
    int prefix = (t == 0) ? 0 : ssum[t - 1];
    for (int i = lo; i < hi; i++) {
        int d = deg[i];
        row_ptr[i] = prefix;
        dis[i] = rsqrtf((float)(d + 1));
        prefix += d;
    }
    if (t == 1023) row_ptr[N] = prefix;
}
__global__ void scatter_kernel(const int* __restrict__ src, const int* __restrict__ dst,
                               const int* __restrict__ row_ptr,
                               int* __restrict__ ctr, unsigned* __restrict__ csr, int E) {
    int e = blockIdx.x * blockDim.x + threadIdx.x;
    if (e >= E) return;
    int s = __ldg(src + e), d = __ldg(dst + e);
    int off = atomicAdd(ctr + d, 1);
    csr[__ldg(row_ptr + d) + off] = (unsigned)s;
}
__global__ void batch_count_kernel(const int* __restrict__ batch, float* __restrict__ gcnt, int N) {
    int i = blockIdx.x * blockDim.x + threadIdx.x;
    if (i >= N) return;
    int b = batch[i];
    unsigned act = __activemask();
    unsigned mask = __match_any_sync(act, b);
    int leader = __ffs(mask) - 1;
    if ((int)(threadIdx.x & 31) == leader)
        atomicAdd(gcnt + b, (float)__popc(mask));
}

// ================= CSR aggregation (8-way unroll; DPL=2 uses one 8B load/edge) =========
template<int DPL>
__global__ void agg_kernel(const int* __restrict__ row_ptr, const unsigned* __restrict__ csr,
                           const float* __restrict__ dis, const __half* __restrict__ xin,
                           __half* __restrict__ xout, int N) {
    int node = (blockIdx.x * blockDim.x + threadIdx.x) >> 5;
    int lane = threadIdx.x & 31;
    if (node >= N) return;
    int beg = __ldg(row_ptr + node), end = __ldg(row_ptr + node + 1);
    float di = __ldg(dis + node);
    float w0 = di * di;

    if (DPL == 1) {
        const __half2* xi = (const __half2*)xin;
        float2 acc;
        {
            float2 v = __half22float2(xi[(long)node * 32 + lane]);
            acc = make_float2(v.x * w0, v.y * w0);
        }
        int j = beg;
        for (; j + 7 < end; j += 8) {
            unsigned s[8]; float w[8];
#pragma unroll
            for (int q = 0; q < 8; q++) s[q] = __ldg(csr + j + q);
#pragma unroll
            for (int q = 0; q < 8; q++) w[q] = __ldg(dis + s[q]) * di;
            float2 u[8];
#pragma unroll
            for (int q = 0; q < 8; q++)
                u[q] = __half22float2(xi[(long)s[q] * 32 + lane]);
#pragma unroll
            for (int q = 0; q < 8; q++) { acc.x += u[q].x * w[q]; acc.y += u[q].y * w[q]; }
        }
        for (; j < end; j++) {
            unsigned s0 = __ldg(csr + j);
            float wa = __ldg(dis + s0) * di;
            float2 u0 = __half22float2(xi[(long)s0 * 32 + lane]);
            acc.x += u0.x * wa; acc.y += u0.y * wa;
        }
        ((__half2*)xout)[(long)node * 32 + lane] = __floats2half2_rn(acc.x, acc.y);
    } else {
        // DPL==2: lane owns 4 contiguous halfs (8 bytes) -> one uint2 load per edge
        const uint2* xi = (const uint2*)xin;
        float4 acc;
        {
            uint2 raw = __ldg(xi + (long)node * 32 + lane);
            float2 a = __half22float2(*(__half2*)&raw.x);
            float2 b = __half22float2(*(__half2*)&raw.y);
            acc = make_float4(a.x * w0, a.y * w0, b.x * w0, b.y * w0);
        }
        int j = beg;
        for (; j + 7 < end; j += 8) {
            unsigned s[8]; float w[8];
#pragma unroll
            for (int q = 0; q < 8; q++) s[q] = __ldg(csr + j + q);
#pragma unroll
            for (int q = 0; q < 8; q++) w[q] = __ldg(dis + s[q]) * di;
            uint2 raw[8];
#pragma unroll
            for (int q = 0; q < 8; q++) raw[q] = __ldg(xi + (long)s[q] * 32 + lane);
#pragma unroll
            for (int q = 0; q < 8; q++) {
                float2 a = __half22float2(*(__half2*)&raw[q].x);
                float2 b = __half22float2(*(__half2*)&raw[q].y);
                acc.x += a.x * w[q]; acc.y += a.y * w[q];
                acc.z += b.x * w[q]; acc.w += b.y * w[q];
            }
        }
        for (; j < end; j++) {
            unsigned s0 = __ldg(csr + j);
            float wa = __ldg(dis + s0) * di;
            uint2 raw = __ldg(xi + (long)s0 * 32 + lane);
            float2 a = __half22float2(*(__half2*)&raw.x);
            float2 b = __half22float2(*(__half2*)&raw.y);
            acc.x += a.x * wa; acc.y += a.y * wa;
            acc.z += b.x * wa; acc.w += b.y * wa;
        }
        __half2 o0 = __floats2half2_rn(acc.x, acc.y);
        __half2 o1 = __floats2half2_rn(acc.z, acc.w);
        uint2 o; o.x = *(uint32_t*)&o0; o.y = *(uint32_t*)&o1;
        ((uint2*)xout)[(long)node * 32 + lane] = o;
    }
}

// ================= head =================
__global__ void head_kernel(const float* __restrict__ Wfc, const float* __restrict__ bfc,
                            const float* __restrict__ Wout, const float* __restrict__ bout,
                            float* __restrict__ out, int out_size) {
    __shared__ float gsh[HID];
    __shared__ float red[HID];
    int gid = blockIdx.x;
    int j   = threadIdx.x;
    float cnt = fmaxf(g_gcnt[gid], 1.0f);
    gsh[j] = g_gsum[gid * HID + j] / cnt;
    __syncthreads();
    float acc = bfc[j];
#pragma unroll 8
    for (int k = 0; k < HID; k++) acc += gsh[k] * Wfc[k * HID + j];
    acc = fmaxf(acc, 0.f);
    red[j] = acc * Wout[j];
    __syncthreads();
#pragma unroll
    for (int s = HID / 2; s > 0; s >>= 1) {
        if (j < s) red[j] += red[j + s];
        __syncthreads();
    }
    if (j == 0) {
        float logit = red[0] + bout[0];
        out[gid] = 1.0f / (1.0f + expf(-logit));
        if (out_size >= 2 * NG) out[NG + gid] = logit;
    }
}

// ================= launch =================
extern "C" void kernel_launch(void* const* d_in, const int* in_sizes, int n_in,
                              void* d_out, int out_size) {
    const int*   tokens = (const int*)  d_in[0];
    const int*   eidx   = (const int*)  d_in[1];
    const int*   batch  = (const int*)  d_in[2];
    const float* emb    = (const float*)d_in[3];
    const float* Wp     = (const float*)d_in[4];
    const float* bp     = (const float*)d_in[5];
    const float* W1     = (const float*)d_in[6];
    const float* b1     = (const float*)d_in[7];
    const float* W2     = (const float*)d_in[8];
    const float* b2     = (const float*)d_in[9];
    const float* Wfc    = (const float*)d_in[10];
    const float* bfc    = (const float*)d_in[11];
    const float* Wout   = (const float*)d_in[12];
    const float* bout   = (const float*)d_in[13];
    float* out = (float*)d_out;

    const int N = in_sizes[2];
    const int E = in_sizes[1] / 2;
    const int* src = eidx;
    const int* dst = eidx + E;

    float *dis, *gsum, *gcnt;
    __half *embWp, *node, *tmp, *x;
    int *ctr, *rowptr; unsigned *csr;
    __nv_bfloat16 *wpth, *wptl;
    __half *wt1h, *wt1l, *wt2h, *wt2l;
    cudaGetSymbolAddress((void**)&embWp,  g_embWp);
    cudaGetSymbolAddress((void**)&node,   g_node);
    cudaGetSymbolAddress((void**)&tmp,    g_tmp);
    cudaGetSymbolAddress((void**)&x,      g_x);
    cudaGetSymbolAddress((void**)&dis,    g_dis);
    cudaGetSymbolAddress((void**)&ctr,    g_ctr);
    cudaGetSymbolAddress((void**)&rowptr, g_rowptr);
    cudaGetSymbolAddress((void**)&csr,    g_csr);
    cudaGetSymbolAddress((void**)&gsum,   g_gsum);
    cudaGetSymbolAddress((void**)&gcnt,   g_gcnt);
    cudaGetSymbolAddress((void**)&wpth,   g_wpth);
    cudaGetSymbolAddress((void**)&wptl,   g_wptl);
    cudaGetSymbolAddress((void**)&wt1h,   g_wt1h);
    cudaGetSymbolAddress((void**)&wt1l,   g_wt1l);
    cudaGetSymbolAddress((void**)&wt2h,   g_wt2h);
    cudaGetSymbolAddress((void**)&wt2l,   g_wt2l);

    static cudaStream_t s2 = nullptr;
    static cudaEvent_t evFork = nullptr, evJoin = nullptr, evPool = nullptr;
    if (s2 == nullptr) {
        cudaStreamCreateWithFlags(&s2, cudaStreamNonBlocking);
        cudaEventCreateWithFlags(&evFork, cudaEventDisableTiming);
        cudaEventCreateWithFlags(&evJoin, cudaEventDisableTiming);
        cudaEventCreateWithFlags(&evPool, cudaEventDisableTiming);
    }

    const int SMEM_V   = 512 + 256 * 144 + 2 * 64  * 144;   //  55808
    const int SMEM_H1  = 512 + 128 * 144 + 2 * 128 * 144;   //  55808
    const int SMEM_H2  = 512 + 128 * 272 + 2 * 128 * 272;   // 104960
    cudaFuncSetAttribute((const void*)mma_gemm_v_kernel<64, 64>,
                         cudaFuncAttributeMaxDynamicSharedMemorySize, SMEM_V);
    cudaFuncSetAttribute((const void*)mma_gemm_h_kernel<64, 1>,
                         cudaFuncAttributeMaxDynamicSharedMemorySize, SMEM_H1);
    cudaFuncSetAttribute((const void*)mma_gemm_h_kernel<128, 2>,
                         cudaFuncAttributeMaxDynamicSharedMemorySize, SMEM_H2);

    // ---- fork: CSR build on s2 (join path carries only rowptr/csr/dis) ----
    cudaEventRecord(evFork, 0);
    cudaStreamWaitEvent(s2, evFork, 0);

    cudaMemsetAsync(ctr, 0, N * sizeof(int), s2);
    hist_kernel<<<(E + 255) / 256, 256, 0, s2>>>(dst, ctr, E);
    scan_kernel<<<1, 1024, 0, s2>>>(ctr, rowptr, dis, N);
    cudaMemsetAsync(ctr, 0, N * sizeof(int), s2);
    scatter_kernel<<<(E + 255) / 256, 256, 0, s2>>>(src, dst, rowptr, ctr, csr, E);
    cudaEventRecord(evJoin, s2);

    // pooling prep AFTER evJoin (runs in layer-1's shadow)
    cudaMemsetAsync(gsum, 0, NG * HID * sizeof(float), s2);
    cudaMemsetAsync(gcnt, 0, NG * sizeof(float), s2);
    batch_count_kernel<<<(N + 255) / 256, 256, 0, s2>>>(batch, gcnt, N);
    cudaEventRecord(evPool, s2);

    // main branch: vocab projection first (critical path), then W1/W2 splits
    convert_w_bf16_kernel<TOK_DIM, NODE_DIM><<<(NODE_DIM * TOK_DIM + 255) / 256, 256>>>(Wp, wpth, wptl);
    mma_gemm_v_kernel<64, 64><<<(VOCAB + 127) / 128, 256, SMEM_V>>>(emb, wpth, wptl, embWp, VOCAB);
    embed_pool_kernel<<<(N * 32 + 255) / 256, 256>>>(tokens, embWp, bp, node, N);
    convert_w_f16_kernel<NODE_DIM, HID><<<(HID * NODE_DIM + 255) / 256, 256>>>(W1, wt1h, wt1l);
    convert_w_f16_kernel<HID, HID><<<(HID * HID + 255) / 256, 256>>>(W2, wt2h, wt2l);

    cudaStreamWaitEvent(0, evJoin, 0);

    // ---- GCN layer 1: aggregate(64) -> f16 GEMM 64->128 + bias + relu -> fp16 x ----
    agg_kernel<1><<<(N * 32 + 255) / 256, 256>>>(rowptr, csr, dis, node, tmp, N);
    mma_gemm_h_kernel<64, 1><<<(N + 127) / 128, 256, SMEM_H1>>>(
        tmp, wt1h, wt1l, b1, x, nullptr, nullptr, N);

    // ---- GCN layer 2: aggregate(128) -> f16 GEMM + bias + relu + pooled epilogue ----
    agg_kernel<2><<<(N * 32 + 255) / 256, 256>>>(rowptr, csr, dis, x, tmp, N);
    cudaStreamWaitEvent(0, evPool, 0);
    mma_gemm_h_kernel<128, 2><<<(N + 127) / 128, 256, SMEM_H2>>>(
        tmp, wt2h, wt2l, b2, nullptr, batch, gsum, N);

    // ---- head ----
    head_kernel<<<NG, HID>>>(Wfc, bfc, Wout, bout, out, out_size);
}

// round 17
// speedup vs baseline: 1.3030x; 1.0152x over previous
#include <cuda_runtime.h>
#include <cuda_bf16.h>
#include <cuda_fp16.h>
#include <math.h>
#include <stdint.h>

// ---------------- problem constants ----------------
#define VOCAB     32000
#define N_TOKENS  16
#define TOK_DIM   64
#define NODE_DIM  64
#define HID       128
#define NG        1024
#define MAXN      100000
#define MAXE      1600000

// ---------------- scratch (static device globals; no allocation) ----------------
__device__ __half g_embWp [VOCAB * NODE_DIM];
__device__ __half g_node  [MAXN * NODE_DIM];
__device__ __half g_tmp   [MAXN * HID];
__device__ __half g_x     [MAXN * HID];
__device__ float  g_dis   [MAXN];
__device__ int    g_ctr   [MAXN];
__device__ int    g_rowptr[MAXN + 1];
__device__ unsigned g_csr [MAXE];
__device__ float  g_gsum  [NG * HID];
__device__ float  g_gcnt  [NG];
__device__ __nv_bfloat16 g_wpth[NODE_DIM * TOK_DIM];
__device__ __nv_bfloat16 g_wptl[NODE_DIM * TOK_DIM];
__device__ __half g_wt1h[HID * NODE_DIM];
__device__ __half g_wt1l[HID * NODE_DIM];
__device__ __half g_wt2h[HID * HID];
__device__ __half g_wt2l[HID * HID];

// ================= helpers =================
__device__ __forceinline__ uint32_t smem_u32(const void* p) {
    uint32_t a;
    asm("{ .reg .u64 t; cvta.to.shared.u64 t, %1; cvt.u32.u64 %0, t; }" : "=r"(a) : "l"(p));
    return a;
}
__device__ __forceinline__ void ldsm4(uint32_t (&r)[4], uint32_t addr) {
    asm volatile("ldmatrix.sync.aligned.m8n8.x4.shared.b16 {%0,%1,%2,%3}, [%4];"
                 : "=r"(r[0]), "=r"(r[1]), "=r"(r[2]), "=r"(r[3]) : "r"(addr));
}
__device__ __forceinline__ void mma16816_bf16(float (&d)[4], const uint32_t (&a)[4],
                                              uint32_t b0, uint32_t b1) {
    asm volatile("mma.sync.aligned.m16n8k16.row.col.f32.bf16.bf16.f32 "
                 "{%0,%1,%2,%3}, {%4,%5,%6,%7}, {%8,%9}, {%0,%1,%2,%3};"
                 : "+f"(d[0]), "+f"(d[1]), "+f"(d[2]), "+f"(d[3])
                 : "r"(a[0]), "r"(a[1]), "r"(a[2]), "r"(a[3]), "r"(b0), "r"(b1));
}
__device__ __forceinline__ void mma16816_f16(float (&d)[4], const uint32_t (&a)[4],
                                             uint32_t b0, uint32_t b1) {
    asm volatile("mma.sync.aligned.m16n8k16.row.col.f32.f16.f16.f32 "
                 "{%0,%1,%2,%3}, {%4,%5,%6,%7}, {%8,%9}, {%0,%1,%2,%3};"
                 : "+f"(d[0]), "+f"(d[1]), "+f"(d[2]), "+f"(d[3])
                 : "r"(a[0]), "r"(a[1]), "r"(a[2]), "r"(a[3]), "r"(b0), "r"(b1));
}
__device__ __forceinline__ float4 u2_to_f4(uint2 raw) {
    float2 a = __half22float2(*(__half2*)&raw.x);
    float2 b = __half22float2(*(__half2*)&raw.y);
    return make_float4(a.x, a.y, b.x, b.y);
}

// ================= W^T split conversions =================
template<int K, int MOUT>
__global__ void convert_w_bf16_kernel(const float* __restrict__ W,
                                      __nv_bfloat16* __restrict__ hi,
                                      __nv_bfloat16* __restrict__ lo) {
    int i = blockIdx.x * blockDim.x + threadIdx.x;
    if (i >= MOUT * K) return;
    int n = i / K, k = i - n * K;
    float f = W[k * MOUT + n];
    __nv_bfloat16 h = __float2bfloat16(f);
    hi[i] = h;
    lo[i] = __float2bfloat16(f - __bfloat162float(h));
}
template<int K, int MOUT>
__global__ void convert_w_f16_kernel(const float* __restrict__ W,
                                     __half* __restrict__ hi,
                                     __half* __restrict__ lo) {
    int i = blockIdx.x * blockDim.x + threadIdx.x;
    if (i >= MOUT * K) return;
    int n = i / K, k = i - n * K;
    float f = W[k * MOUT + n];
    __half h = __float2half_rn(f);
    hi[i] = h;
    lo[i] = __float2half_rn(f - __half2float(h));
}

// ====== vocab GEMM (fp32 input, split-bf16, fp16 out) ======
template<int K, int MOUT>
__global__ __launch_bounds__(256) void mma_gemm_v_kernel(
    const float* __restrict__ X,
    const __nv_bfloat16* __restrict__ Wth, const __nv_bfloat16* __restrict__ Wtl,
    __half* __restrict__ Y, int N) {
    extern __shared__ char smem[];
    constexpr int P    = K * 2 + 16;
    constexpr int A_HI = 512;
    constexpr int A_LO = A_HI + 128 * P;
    constexpr int B_HI = A_LO + 128 * P;
    constexpr int B_LO = B_HI + MOUT * P;
    constexpr int NT   = MOUT / 16;
    constexpr int NT2  = NT / 2;
    constexpr int KS   = K / 16;
    constexpr int KQ   = K / 4;

    const int tid = threadIdx.x, wid = tid >> 5, lane = tid & 31;
    const int row0 = blockIdx.x * 128;

    for (int idx = tid; idx < 128 * KQ; idx += 256) {
        int r = idx / KQ, kq = idx - r * KQ;
        int row = row0 + r;
        float4 v = (row < N) ? *(const float4*)(X + (long)row * K + kq * 4)
                             : make_float4(0.f, 0.f, 0.f, 0.f);
        float f[4] = {v.x, v.y, v.z, v.w};
        __nv_bfloat16 h[4], l[4];
#pragma unroll
        for (int j = 0; j < 4; j++) {
            h[j] = __float2bfloat16(f[j]);
            l[j] = __float2bfloat16(f[j] - __bfloat162float(h[j]));
        }
        __nv_bfloat162 h01(h[0], h[1]), h23(h[2], h[3]);
        __nv_bfloat162 l01(l[0], l[1]), l23(l[2], l[3]);
        *(uint2*)(smem + A_HI + r * P + kq * 8) = make_uint2(*(uint32_t*)&h01, *(uint32_t*)&h23);
        *(uint2*)(smem + A_LO + r * P + kq * 8) = make_uint2(*(uint32_t*)&l01, *(uint32_t*)&l23);
    }
    for (int idx = tid; idx < MOUT * KQ; idx += 256) {
        int r = idx / KQ, kq = idx - r * KQ;
        *(uint2*)(smem + B_HI + r * P + kq * 8) = *(const uint2*)(Wth + r * K + kq * 4);
        *(uint2*)(smem + B_LO + r * P + kq * 8) = *(const uint2*)(Wtl + r * K + kq * 4);
    }
    __syncthreads();

    const int wm = (wid >> 1) * 32;
    const int wn = (wid & 1) * (MOUT / 2);
    const int grp = lane >> 3, rr = lane & 7;
    const uint32_t sb = smem_u32(smem);
    const uint32_t aH = sb + A_HI + (uint32_t)(wm + (grp & 1) * 8 + rr) * P + ((grp >> 1) * 8) * 2;
    const uint32_t aL = aH + (uint32_t)(A_LO - A_HI);
    const uint32_t bH = sb + B_HI + (uint32_t)(wn + (grp >> 1) * 8 + rr) * P + ((grp & 1) * 8) * 2;
    const uint32_t bL = bH + (uint32_t)(B_LO - B_HI);

    float acc[2][NT][4];
#pragma unroll
    for (int mt = 0; mt < 2; mt++)
#pragma unroll
        for (int nt = 0; nt < NT; nt++)
#pragma unroll
            for (int j = 0; j < 4; j++) acc[mt][nt][j] = 0.f;

#pragma unroll
    for (int ks = 0; ks < KS; ks++) {
        uint32_t ah[2][4], al[2][4], bh[NT2][4], bl[NT2][4];
#pragma unroll
        for (int mt = 0; mt < 2; mt++) {
            ldsm4(ah[mt], aH + mt * 16 * P + ks * 32);
            ldsm4(al[mt], aL + mt * 16 * P + ks * 32);
        }
#pragma unroll
        for (int nt2 = 0; nt2 < NT2; nt2++) {
            ldsm4(bh[nt2], bH + nt2 * 16 * P + ks * 32);
            ldsm4(bl[nt2], bL + nt2 * 16 * P + ks * 32);
        }
#pragma unroll
        for (int mt = 0; mt < 2; mt++)
#pragma unroll
            for (int nt2 = 0; nt2 < NT2; nt2++)
#pragma unroll
                for (int h = 0; h < 2; h++) {
                    float (&d)[4] = acc[mt][nt2 * 2 + h];
                    mma16816_bf16(d, ah[mt], bh[nt2][h * 2], bh[nt2][h * 2 + 1]);
                    mma16816_bf16(d, ah[mt], bl[nt2][h * 2], bl[nt2][h * 2 + 1]);
                    mma16816_bf16(d, al[mt], bh[nt2][h * 2], bh[nt2][h * 2 + 1]);
                }
    }

    const int lrow = lane >> 2;
    const int lcol = (lane & 3) * 2;
#pragma unroll
    for (int mt = 0; mt < 2; mt++) {
        int row = row0 + wm + mt * 16 + lrow;
#pragma unroll
        for (int nt = 0; nt < NT; nt++) {
            int col = wn + nt * 8 + lcol;
            if (row < N)
                *(__half2*)(Y + (long)row * MOUT + col) =
                    __floats2half2_rn(acc[mt][nt][0], acc[mt][nt][1]);
            if (row + 8 < N)
                *(__half2*)(Y + (long)(row + 8) * MOUT + col) =
                    __floats2half2_rn(acc[mt][nt][2], acc[mt][nt][3]);
        }
    }
}

// ====== layer GEMM: fp16 A (exact) x split-fp16 W, 2 MMAs per step ======
template<int K, int MODE>
__global__ __launch_bounds__(256) void mma_gemm_h_kernel(
    const __half* __restrict__ X,
    const __half* __restrict__ Wth, const __half* __restrict__ Wtl,
    const float* __restrict__ bias, __half* __restrict__ Y,
    const int* __restrict__ batch, float* __restrict__ gsum, int N) {
    extern __shared__ char smem[];
    constexpr int MOUT = HID;
    constexpr int P    = K * 2 + 16;
    constexpr int A_T  = 512;
    constexpr int B_HI = A_T + 128 * P;
    constexpr int B_LO = B_HI + MOUT * P;
    constexpr int NT   = MOUT / 16;
    constexpr int NT2  = NT / 2;
    constexpr int KS   = K / 16;
    constexpr int KQ   = K / 4;

    const int tid = threadIdx.x, wid = tid >> 5, lane = tid & 31;
    const int row0 = blockIdx.x * 128;
    float* bs = (float*)smem;
    if (tid < MOUT) bs[tid] = bias[tid];

    for (int idx = tid; idx < 128 * KQ; idx += 256) {
        int r = idx / KQ, kq = idx - r * KQ;
        int row = row0 + r;
        uint2 raw = (row < N) ? *(const uint2*)(X + (long)row * K + kq * 4)
                              : make_uint2(0u, 0u);
        *(uint2*)(smem + A_T + r * P + kq * 8) = raw;
    }
    for (int idx = tid; idx < MOUT * KQ; idx += 256) {
        int r = idx / KQ, kq = idx - r * KQ;
        *(uint2*)(smem + B_HI + r * P + kq * 8) = *(const uint2*)(Wth + r * K + kq * 4);
        *(uint2*)(smem + B_LO + r * P + kq * 8) = *(const uint2*)(Wtl + r * K + kq * 4);
    }
    __syncthreads();

    const int wm = (wid >> 1) * 32;
    const int wn = (wid & 1) * (MOUT / 2);
    const int grp = lane >> 3, rr = lane & 7;
    const uint32_t sb = smem_u32(smem);
    const uint32_t aT = sb + A_T + (uint32_t)(wm + (grp & 1) * 8 + rr) * P + ((grp >> 1) * 8) * 2;
    const uint32_t bH = sb + B_HI + (uint32_t)(wn + (grp >> 1) * 8 + rr) * P + ((grp & 1) * 8) * 2;
    const uint32_t bL = bH + (uint32_t)(B_LO - B_HI);

    float acc[2][NT][4];
#pragma unroll
    for (int mt = 0; mt < 2; mt++)
#pragma unroll
        for (int nt = 0; nt < NT; nt++)
#pragma unroll
            for (int j = 0; j < 4; j++) acc[mt][nt][j] = 0.f;

#pragma unroll
    for (int ks = 0; ks < KS; ks++) {
        uint32_t a[2][4], bh[NT2][4], bl[NT2][4];
#pragma unroll
        for (int mt = 0; mt < 2; mt++)
            ldsm4(a[mt], aT + mt * 16 * P + ks * 32);
#pragma unroll
        for (int nt2 = 0; nt2 < NT2; nt2++) {
            ldsm4(bh[nt2], bH + nt2 * 16 * P + ks * 32);
            ldsm4(bl[nt2], bL + nt2 * 16 * P + ks * 32);
        }
#pragma unroll
        for (int mt = 0; mt < 2; mt++)
#pragma unroll
            for (int nt2 = 0; nt2 < NT2; nt2++)
#pragma unroll
                for (int h = 0; h < 2; h++) {
                    float (&d)[4] = acc[mt][nt2 * 2 + h];
                    mma16816_f16(d, a[mt], bh[nt2][h * 2], bh[nt2][h * 2 + 1]);
                    mma16816_f16(d, a[mt], bl[nt2][h * 2], bl[nt2][h * 2 + 1]);
                }
    }

    const int lrow = lane >> 2;
    const int lcol = (lane & 3) * 2;
#pragma unroll
    for (int mt = 0; mt < 2; mt++) {
        int row = row0 + wm + mt * 16 + lrow;
        int b0i = 0, b1i = 0;
        if (MODE == 2) {
            b0i = (row < N)     ? __ldg(batch + row)     : -1;
            b1i = (row + 8 < N) ? __ldg(batch + row + 8) : -1;
        }
#pragma unroll
        for (int nt = 0; nt < NT; nt++) {
            int col = wn + nt * 8 + lcol;
            float c0 = bs[col], c1 = bs[col + 1];
            float2 v0 = make_float2(fmaxf(acc[mt][nt][0] + c0, 0.f),
                                    fmaxf(acc[mt][nt][1] + c1, 0.f));
            float2 v1 = make_float2(fmaxf(acc[mt][nt][2] + c0, 0.f),
                                    fmaxf(acc[mt][nt][3] + c1, 0.f));
            if (MODE == 2) {
                if (b0i >= 0) {
                    float* p = gsum + b0i * MOUT + col;
                    asm volatile("red.global.add.v2.f32 [%0], {%1,%2};"
                                 :: "l"(p), "f"(v0.x), "f"(v0.y) : "memory");
                }
                if (b1i >= 0) {
                    float* p = gsum + b1i * MOUT + col;
                    asm volatile("red.global.add.v2.f32 [%0], {%1,%2};"
                                 :: "l"(p), "f"(v1.x), "f"(v1.y) : "memory");
                }
            } else {
                if (row < N)
                    *(__half2*)(Y + (long)row * MOUT + col) = __floats2half2_rn(v0.x, v0.y);
                if (row + 8 < N)
                    *(__half2*)(Y + (long)(row + 8) * MOUT + col) = __floats2half2_rn(v1.x, v1.y);
            }
        }
    }
}

// ============ token gather + mean pool: half-warp per token, uint2 lanes ============
__global__ void embed_pool_kernel(const int* __restrict__ tokens,
                                  const __half* __restrict__ embWp,
                                  const float* __restrict__ bp,
                                  __half* __restrict__ node, int N) {
    int warp = (blockIdx.x * blockDim.x + threadIdx.x) >> 5;
    int lane = threadIdx.x & 31;
    if (warp >= N) return;
    const int half = lane >> 4;
    const int l16  = lane & 15;
    const int* tp = tokens + warp * N_TOKENS;
    const uint2* e2 = (const uint2*)embWp;   // row = 16 uint2 (64 halfs)
    float4 acc = make_float4(0.f, 0.f, 0.f, 0.f);
#pragma unroll
    for (int t = 0; t < N_TOKENS; t += 2) {
        int tok = __ldg(tp + t + half);
        float4 f = u2_to_f4(__ldg(e2 + (long)tok * 16 + l16));
        acc.x += f.x; acc.y += f.y; acc.z += f.z; acc.w += f.w;
    }
    acc.x += __shfl_xor_sync(0xFFFFFFFFu, acc.x, 16);
    acc.y += __shfl_xor_sync(0xFFFFFFFFu, acc.y, 16);
    acc.z += __shfl_xor_sync(0xFFFFFFFFu, acc.z, 16);
    acc.w += __shfl_xor_sync(0xFFFFFFFFu, acc.w, 16);
    if (half == 0) {
        float4 bv = *(const float4*)(bp + l16 * 4);
        const float inv = 1.0f / N_TOKENS;
        __half2 o0 = __floats2half2_rn(acc.x * inv + bv.x, acc.y * inv + bv.y);
        __half2 o1 = __floats2half2_rn(acc.z * inv + bv.z, acc.w * inv + bv.w);
        uint2 o; o.x = *(uint32_t*)&o0; o.y = *(uint32_t*)&o1;
        ((uint2*)node)[(long)warp * 16 + l16] = o;
    }
}

// ================= CSR build =================
__global__ void hist_kernel(const int* __restrict__ dst, int* __restrict__ ctr, int E) {
    int e = blockIdx.x * blockDim.x + threadIdx.x;
    if (e < E) atomicAdd(ctr + dst[e], 1);
}
__global__ void scan_kernel(const int* __restrict__ deg, int* __restrict__ row_ptr,
                            float* __restrict__ dis, int N) {
    __shared__ int ssum[1024];
    int t = threadIdx.x;
    int chunk = (N + 1023) / 1024;
    int lo = t * chunk;
    int hi = lo + chunk; if (hi > N) hi = N; if (lo > N) lo = N;
    int s = 0;
    for (int i = lo; i < hi; i++) s += deg[i];
    ssum[t] = s;
    __syncthreads();
    for (int off = 1; off < 1024; off <<= 1) {
        int v = (t >= off) ? ssum[t - off] : 0;
        __syncthreads();
        ssum[t] += v;
        __syncthreads();
    }
    int prefix = (t == 0) ? 0 : ssum[t - 1];
    for (int i = lo; i < hi; i++) {
        int d = deg[i];
        row_ptr[i] = prefix;
        dis[i] = rsqrtf((float)(d + 1));
        prefix += d;
    }
    if (t == 1023) row_ptr[N] = prefix;
}
__global__ void scatter_kernel(const int* __restrict__ src, const int* __restrict__ dst,
                               const int* __restrict__ row_ptr,
                               int* __restrict__ ctr, unsigned* __restrict__ csr, int E) {
    int e = blockIdx.x * blockDim.x + threadIdx.x;
    if (e >= E) return;
    int s = __ldg(src + e), d = __ldg(dst + e);
    int off = atomicAdd(ctr + d, 1);
    csr[__ldg(row_ptr + d) + off] = (unsigned)s;
}
__global__ void batch_count_kernel(const int* __restrict__ batch, float* __restrict__ gcnt, int N) {
    int i = blockIdx.x * blockDim.x + threadIdx.x;
    if (i >= N) return;
    int b = batch[i];
    unsigned act = __activemask();
    unsigned mask = __match_any_sync(act, b);
    int leader = __ffs(mask) - 1;
    if ((int)(threadIdx.x & 31) == leader)
        atomicAdd(gcnt + b, (float)__popc(mask));
}

// ===== agg64: half-warp per edge (2 edges/iter), one uint2 load per lane per edge =====
__global__ void agg64_kernel(const int* __restrict__ row_ptr, const unsigned* __restrict__ csr,
                             const float* __restrict__ dis, const __half* __restrict__ xin,
                             __half* __restrict__ xout, int N) {
    int node = (blockIdx.x * blockDim.x + threadIdx.x) >> 5;
    int lane = threadIdx.x & 31;
    if (node >= N) return;
    const int half = lane >> 4;
    const int l16  = lane & 15;
    int beg = __ldg(row_ptr + node), end = __ldg(row_ptr + node + 1);
    float di = __ldg(dis + node);
    const uint2* xi = (const uint2*)xin;   // row = 16 uint2
    float4 acc = make_float4(0.f, 0.f, 0.f, 0.f);

    int j = beg;
    for (; j + 7 < end; j += 8) {
        // lanes 0-15: edges j, j+2, j+4, j+6; lanes 16-31: j+1, j+3, j+5, j+7
        unsigned s[4]; float w[4];
#pragma unroll
        for (int q = 0; q < 4; q++) s[q] = __ldg(csr + j + 2 * q + half);
#pragma unroll
        for (int q = 0; q < 4; q++) w[q] = __ldg(dis + s[q]) * di;
        uint2 raw[4];
#pragma unroll
        for (int q = 0; q < 4; q++) raw[q] = __ldg(xi + (long)s[q] * 16 + l16);
#pragma unroll
        for (int q = 0; q < 4; q++) {
            float4 f = u2_to_f4(raw[q]);
            acc.x += f.x * w[q]; acc.y += f.y * w[q];
            acc.z += f.z * w[q]; acc.w += f.w * w[q];
        }
    }
    for (; j < end; j++) {
        if (half == 0) {
            unsigned s0 = __ldg(csr + j);
            float wa = __ldg(dis + s0) * di;
            float4 f = u2_to_f4(__ldg(xi + (long)s0 * 16 + l16));
            acc.x += f.x * wa; acc.y += f.y * wa;
            acc.z += f.z * wa; acc.w += f.w * wa;
        }
    }
    acc.x += __shfl_xor_sync(0xFFFFFFFFu, acc.x, 16);
    acc.y += __shfl_xor_sync(0xFFFFFFFFu, acc.y, 16);
    acc.z += __shfl_xor_sync(0xFFFFFFFFu, acc.z, 16);
    acc.w += __shfl_xor_sync(0xFFFFFFFFu, acc.w, 16);
    if (half == 0) {
        float w0 = di * di;
        float4 f = u2_to_f4(__ldg(xi + (long)node * 16 + l16));
        acc.x += f.x * w0; acc.y += f.y * w0;
        acc.z += f.z * w0; acc.w += f.w * w0;
        __half2 o0 = __floats2half2_rn(acc.x, acc.y);
        __half2 o1 = __floats2half2_rn(acc.z, acc.w);
        uint2 o; o.x = *(uint32_t*)&o0; o.y = *(uint32_t*)&o1;
        ((uint2*)xout)[(long)node * 16 + l16] = o;
    }
}

// ===== agg128: full warp per edge, one uint2 load per lane per edge (R16 form) =====
__global__ void agg128_kernel(const int* __restrict__ row_ptr, const unsigned* __restrict__ csr,
                              const float* __restrict__ dis, const __half* __restrict__ xin,
                              __half* __restrict__ xout, int N) {
    int node = (blockIdx.x * blockDim.x + threadIdx.x) >> 5;
    int lane = threadIdx.x & 31;
    if (node >= N) return;
    int beg = __ldg(row_ptr + node), end = __ldg(row_ptr + node + 1);
    float di = __ldg(dis + node);
    float w0 = di * di;
    const uint2* xi = (const uint2*)xin;   // row = 32 uint2 (128 halfs)
    float4 acc;
    {
        float4 f = u2_to_f4(__ldg(xi + (long)node * 32 + lane));
        acc = make_float4(f.x * w0, f.y * w0, f.z * w0, f.w * w0);
    }
    int j = beg;
    for (; j + 7 < end; j += 8) {
        unsigned s[8]; float w[8];
#pragma unroll
        for (int q = 0; q < 8; q++) s[q] = __ldg(csr + j + q);
#pragma unroll
        for (int q = 0; q < 8; q++) w[q] = __ldg(dis + s[q]) * di;
        uint2 raw[8];
#pragma unroll
        for (int q = 0; q < 8; q++) raw[q] = __ldg(xi + (long)s[q] * 32 + lane);
#pragma unroll
        for (int q = 0; q < 8; q++) {
            float4 f = u2_to_f4(raw[q]);
            acc.x += f.x * w[q]; acc.y += f.y * w[q];
            acc.z += f.z * w[q]; acc.w += f.w * w[q];
        }
    }
    for (; j < end; j++) {
        unsigned s0 = __ldg(csr + j);
        float wa = __ldg(dis + s0) * di;
        float4 f = u2_to_f4(__ldg(xi + (long)s0 * 32 + lane));
        acc.x += f.x * wa; acc.y += f.y * wa;
        acc.z += f.z * wa; acc.w += f.w * wa;
    }
    __half2 o0 = __floats2half2_rn(acc.x, acc.y);
    __half2 o1 = __floats2half2_rn(acc.z, acc.w);
    uint2 o; o.x = *(uint32_t*)&o0; o.y = *(uint32_t*)&o1;
    ((uint2*)xout)[(long)node * 32 + lane] = o;
}

// ================= head =================
__global__ void head_kernel(const float* __restrict__ Wfc, const float* __restrict__ bfc,
                            const float* __restrict__ Wout, const float* __restrict__ bout,
                            float* __restrict__ out, int out_size) {
    __shared__ float gsh[HID];
    __shared__ float red[HID];
    int gid = blockIdx.x;
    int j   = threadIdx.x;
    float cnt = fmaxf(g_gcnt[gid], 1.0f);
    gsh[j] = g_gsum[gid * HID + j] / cnt;
    __syncthreads();
    float acc = bfc[j];
#pragma unroll 8
    for (int k = 0; k < HID; k++) acc += gsh[k] * Wfc[k * HID + j];
    acc = fmaxf(acc, 0.f);
    red[j] = acc * Wout[j];
    __syncthreads();
#pragma unroll
    for (int s = HID / 2; s > 0; s >>= 1) {
        if (j < s) red[j] += red[j + s];
        __syncthreads();
    }
    if (j == 0) {
        float logit = red[0] + bout[0];
        out[gid] = 1.0f / (1.0f + expf(-logit));
        if (out_size >= 2 * NG) out[NG + gid] = logit;
    }
}

// ================= launch =================
extern "C" void kernel_launch(void* const* d_in, const int* in_sizes, int n_in,
                              void* d_out, int out_size) {
    const int*   tokens = (const int*)  d_in[0];
    const int*   eidx   = (const int*)  d_in[1];
    const int*   batch  = (const int*)  d_in[2];
    const float* emb    = (const float*)d_in[3];
    const float* Wp     = (const float*)d_in[4];
    const float* bp     = (const float*)d_in[5];
    const float* W1     = (const float*)d_in[6];
    const float* b1     = (const float*)d_in[7];
    const float* W2     = (const float*)d_in[8];
    const float* b2     = (const float*)d_in[9];
    const float* Wfc    = (const float*)d_in[10];
    const float* bfc    = (const float*)d_in[11];
    const float* Wout   = (const float*)d_in[12];
    const float* bout   = (const float*)d_in[13];
    float* out = (float*)d_out;

    const int N = in_sizes[2];
    const int E = in_sizes[1] / 2;
    const int* src = eidx;
    const int* dst = eidx + E;

    float *dis, *gsum, *gcnt;
    __half *embWp, *node, *tmp, *x;
    int *ctr, *rowptr; unsigned *csr;
    __nv_bfloat16 *wpth, *wptl;
    __half *wt1h, *wt1l, *wt2h, *wt2l;
    cudaGetSymbolAddress((void**)&embWp,  g_embWp);
    cudaGetSymbolAddress((void**)&node,   g_node);
    cudaGetSymbolAddress((void**)&tmp,    g_tmp);
    cudaGetSymbolAddress((void**)&x,      g_x);
    cudaGetSymbolAddress((void**)&dis,    g_dis);
    cudaGetSymbolAddress((void**)&ctr,    g_ctr);
    cudaGetSymbolAddress((void**)&rowptr, g_rowptr);
    cudaGetSymbolAddress((void**)&csr,    g_csr);
    cudaGetSymbolAddress((void**)&gsum,   g_gsum);
    cudaGetSymbolAddress((void**)&gcnt,   g_gcnt);
    cudaGetSymbolAddress((void**)&wpth,   g_wpth);
    cudaGetSymbolAddress((void**)&wptl,   g_wptl);
    cudaGetSymbolAddress((void**)&wt1h,   g_wt1h);
    cudaGetSymbolAddress((void**)&wt1l,   g_wt1l);
    cudaGetSymbolAddress((void**)&wt2h,   g_wt2h);
    cudaGetSymbolAddress((void**)&wt2l,   g_wt2l);

    static cudaStream_t s2 = nullptr;
    static cudaEvent_t evFork = nullptr, evJoin = nullptr, evPool = nullptr;
    if (s2 == nullptr) {
        cudaStreamCreateWithFlags(&s2, cudaStreamNonBlocking);
        cudaEventCreateWithFlags(&evFork, cudaEventDisableTiming);
        cudaEventCreateWithFlags(&evJoin, cudaEventDisableTiming);
        cudaEventCreateWithFlags(&evPool, cudaEventDisableTiming);
    }

    const int SMEM_V   = 512 + 256 * 144 + 2 * 64  * 144;   //  55808
    const int SMEM_H1  = 512 + 128 * 144 + 2 * 128 * 144;   //  55808
    const int SMEM_H2  = 512 + 128 * 272 + 2 * 128 * 272;   // 104960
    cudaFuncSetAttribute((const void*)mma_gemm_v_kernel<64, 64>,
                         cudaFuncAttributeMaxDynamicSharedMemorySize, SMEM_V);
    cudaFuncSetAttribute((const void*)mma_gemm_h_kernel<64, 1>,
                         cudaFuncAttributeMaxDynamicSharedMemorySize, SMEM_H1);
    cudaFuncSetAttribute((const void*)mma_gemm_h_kernel<128, 2>,
                         cudaFuncAttributeMaxDynamicSharedMemorySize, SMEM_H2);

    // ---- fork: CSR build on s2 (join path carries only rowptr/csr/dis) ----
    cudaEventRecord(evFork, 0);
    cudaStreamWaitEvent(s2, evFork, 0);

    cudaMemsetAsync(ctr, 0, N * sizeof(int), s2);
    hist_kernel<<<(E + 255) / 256, 256, 0, s2>>>(dst, ctr, E);
    scan_kernel<<<1, 1024, 0, s2>>>(ctr, rowptr, dis, N);
    cudaMemsetAsync(ctr, 0, N * sizeof(int), s2);
    scatter_kernel<<<(E + 255) / 256, 256, 0, s2>>>(src, dst, rowptr, ctr, csr, E);
    cudaEventRecord(evJoin, s2);

    // pooling prep AFTER evJoin (runs in layer-1's shadow)
    cudaMemsetAsync(gsum, 0, NG * HID * sizeof(float), s2);
    cudaMemsetAsync(gcnt, 0, NG * sizeof(float), s2);
    batch_count_kernel<<<(N + 255) / 256, 256, 0, s2>>>(batch, gcnt, N);
    cudaEventRecord(evPool, s2);

    // main branch: vocab projection first (critical path), then W1/W2 splits
    convert_w_bf16_kernel<TOK_DIM, NODE_DIM><<<(NODE_DIM * TOK_DIM + 255) / 256, 256>>>(Wp, wpth, wptl);
    mma_gemm_v_kernel<64, 64><<<(VOCAB + 127) / 128, 256, SMEM_V>>>(emb, wpth, wptl, embWp, VOCAB);
    embed_pool_kernel<<<(N * 32 + 255) / 256, 256>>>(tokens, embWp, bp, node, N);
    convert_w_f16_kernel<NODE_DIM, HID><<<(HID * NODE_DIM + 255) / 256, 256>>>(W1, wt1h, wt1l);
    convert_w_f16_kernel<HID, HID><<<(HID * HID + 255) / 256, 256>>>(W2, wt2h, wt2l);

    cudaStreamWaitEvent(0, evJoin, 0);

    // ---- GCN layer 1: aggregate(64) -> f16 GEMM 64->128 + bias + relu -> fp16 x ----
    agg64_kernel<<<(N * 32 + 255) / 256, 256>>>(rowptr, csr, dis, node, tmp, N);
    mma_gemm_h_kernel<64, 1><<<(N + 127) / 128, 256, SMEM_H1>>>(
        tmp, wt1h, wt1l, b1, x, nullptr, nullptr, N);

    // ---- GCN layer 2: aggregate(128) -> f16 GEMM + bias + relu + pooled epilogue ----
    agg128_kernel<<<(N * 32 + 255) / 256, 256>>>(rowptr, csr, dis, x, tmp, N);
    cudaStreamWaitEvent(0, evPool, 0);
    mma_gemm_h_kernel<128, 2><<<(N + 127) / 128, 256, SMEM_H2>>>(
        tmp, wt2h, wt2l, b2, nullptr, batch, gsum, N);

    // ---- head ----
    head_kernel<<<NG, HID>>>(Wfc, bfc, Wout, bout, out, out_size);
}